// round 1
// baseline (speedup 1.0000x reference)
#include <cuda_runtime.h>
#include <cuda_bf16.h>
#include <cfloat>
#include <cstdint>

// Problem constants
#define BB 32768
#define AA 16
#define HH 256
#define DD 128
#define KK 2048

// ---------------------------------------------------------------------------
// Scratch (device globals: no cudaMalloc allowed)
// ---------------------------------------------------------------------------
__device__ float  g_h1[BB * HH];     // encoder h1 / decoder d1 (reused)
__device__ float  g_h2[BB * HH];     // encoder h2 / decoder d2 (reused)
__device__ float  g_enc[BB * DD];
__device__ float  g_q[BB * DD];
__device__ int    g_idx[BB];
__device__ float  g_esq[KK];
__device__ double g_sums[2];         // [0]=vq sum (enc-q)^2, [1]=recons sum

// ---------------------------------------------------------------------------
// Helpers
// ---------------------------------------------------------------------------
__device__ __forceinline__ void block_reduce_add_to(float v, double* target) {
    __shared__ float sbuf[32];
    int lane = threadIdx.x & 31;
    int wid  = threadIdx.x >> 5;
#pragma unroll
    for (int o = 16; o; o >>= 1) v += __shfl_xor_sync(0xffffffffu, v, o);
    if (lane == 0) sbuf[wid] = v;
    __syncthreads();
    if (wid == 0) {
        int nw = blockDim.x >> 5;
        v = (lane < nw) ? sbuf[lane] : 0.0f;
#pragma unroll
        for (int o = 16; o; o >>= 1) v += __shfl_xor_sync(0xffffffffu, v, o);
        if (lane == 0) atomicAdd(target, (double)v);
    }
}

__global__ void zero_sums_kernel() {
    if (threadIdx.x < 2) g_sums[threadIdx.x] = 0.0;
}

// ---------------------------------------------------------------------------
// Generic fused GEMM: Y[B][N] = act(X[B][K] @ W[N][K]^T + bias)
// BM=128, BN=128, BK=16, 256 threads, 8x8 micro-tile.
// ---------------------------------------------------------------------------
template <int N, int K, bool RELU>
__global__ __launch_bounds__(256, 2)
void gemm_bias_kernel(const float* __restrict__ X, const float* __restrict__ W,
                      const float* __restrict__ bias, float* __restrict__ Y) {
    constexpr int BM = 128, BN = 128, BK = 16, TM = 8, TN = 8;
    __shared__ float As[BK][BM];   // [k][m]
    __shared__ float Bs[BK][BN];   // [k][n]

    const int bm  = blockIdx.x * BM;
    const int bn  = blockIdx.y * BN;
    const int tid = threadIdx.x;
    const int tr  = tid >> 4;      // 0..15
    const int tc  = tid & 15;      // 0..15

    float acc[TM][TN];
#pragma unroll
    for (int i = 0; i < TM; i++)
#pragma unroll
        for (int j = 0; j < TN; j++) acc[i][j] = 0.0f;

    for (int k0 = 0; k0 < K; k0 += BK) {
#pragma unroll
        for (int t = 0; t < 2; t++) {
            int idx = tid + t * 256;                // 512 float4 = 128x16
            int m   = idx >> 2;
            int kq  = (idx & 3) << 2;
            float4 v = *reinterpret_cast<const float4*>(
                X + (size_t)(bm + m) * K + k0 + kq);
            As[kq + 0][m] = v.x; As[kq + 1][m] = v.y;
            As[kq + 2][m] = v.z; As[kq + 3][m] = v.w;
        }
#pragma unroll
        for (int t = 0; t < 2; t++) {
            int idx = tid + t * 256;
            int n   = idx >> 2;
            int kq  = (idx & 3) << 2;
            float4 v = *reinterpret_cast<const float4*>(
                W + (size_t)(bn + n) * K + k0 + kq);
            Bs[kq + 0][n] = v.x; Bs[kq + 1][n] = v.y;
            Bs[kq + 2][n] = v.z; Bs[kq + 3][n] = v.w;
        }
        __syncthreads();
#pragma unroll
        for (int k = 0; k < BK; k++) {
            float a[TM], b[TN];
            *reinterpret_cast<float4*>(&a[0]) = *reinterpret_cast<float4*>(&As[k][tr * TM]);
            *reinterpret_cast<float4*>(&a[4]) = *reinterpret_cast<float4*>(&As[k][tr * TM + 4]);
            *reinterpret_cast<float4*>(&b[0]) = *reinterpret_cast<float4*>(&Bs[k][tc * TN]);
            *reinterpret_cast<float4*>(&b[4]) = *reinterpret_cast<float4*>(&Bs[k][tc * TN + 4]);
#pragma unroll
            for (int i = 0; i < TM; i++)
#pragma unroll
                for (int j = 0; j < TN; j++) acc[i][j] += a[i] * b[j];
        }
        __syncthreads();
    }

    float bv[TN];
#pragma unroll
    for (int j = 0; j < TN; j++) bv[j] = __ldg(&bias[bn + tc * TN + j]);

#pragma unroll
    for (int i = 0; i < TM; i++) {
        int m = bm + tr * TM + i;
#pragma unroll
        for (int j = 0; j < TN; j += 4) {
            float4 o;
            o.x = acc[i][j + 0] + bv[j + 0];
            o.y = acc[i][j + 1] + bv[j + 1];
            o.z = acc[i][j + 2] + bv[j + 2];
            o.w = acc[i][j + 3] + bv[j + 3];
            if (RELU) {
                o.x = fmaxf(o.x, 0.0f); o.y = fmaxf(o.y, 0.0f);
                o.z = fmaxf(o.z, 0.0f); o.w = fmaxf(o.w, 0.0f);
            }
            *reinterpret_cast<float4*>(Y + (size_t)m * N + bn + tc * TN + j) = o;
        }
    }
}

// ---------------------------------------------------------------------------
// |E[n]|^2
// ---------------------------------------------------------------------------
__global__ void esq_kernel(const float* __restrict__ E) {
    int n = blockIdx.x * blockDim.x + threadIdx.x;
    if (n >= KK) return;
    const float4* r = reinterpret_cast<const float4*>(E + (size_t)n * DD);
    float s = 0.0f;
#pragma unroll
    for (int i = 0; i < DD / 4; i++) {
        float4 v = r[i];
        s += v.x * v.x + v.y * v.y + v.z * v.z + v.w * v.w;
    }
    g_esq[n] = s;
}

// ---------------------------------------------------------------------------
// Nearest-codebook argmin: per block 128 rows, loops all 2048 codes in
// 128-code chunks, GEMM-style register tiling, fused min-reduce.
// d2' = |E[n]|^2 - 2*enc.E[n]  (row-constant |enc|^2 dropped)
// ---------------------------------------------------------------------------
__global__ __launch_bounds__(256, 2)
void dist_argmin_kernel(const float* __restrict__ enc, const float* __restrict__ E) {
    constexpr int BM = 128, BN = 128, BK = 16, TM = 8, TN = 8;
    __shared__ float As[BK][BM];
    __shared__ float Es[BK][BN];
    __shared__ float red_v[BM][16];
    __shared__ int   red_i[BM][16];

    const int bm  = blockIdx.x * BM;
    const int tid = threadIdx.x;
    const int tr  = tid >> 4;
    const int tc  = tid & 15;

    float bestv[TM];
    int   besti[TM];
#pragma unroll
    for (int i = 0; i < TM; i++) { bestv[i] = FLT_MAX; besti[i] = 0; }

    for (int n0 = 0; n0 < KK; n0 += BN) {
        float acc[TM][TN];
#pragma unroll
        for (int i = 0; i < TM; i++)
#pragma unroll
            for (int j = 0; j < TN; j++) acc[i][j] = 0.0f;

        for (int k0 = 0; k0 < DD; k0 += BK) {
#pragma unroll
            for (int t = 0; t < 2; t++) {
                int idx = tid + t * 256;
                int m   = idx >> 2;
                int kq  = (idx & 3) << 2;
                float4 v = *reinterpret_cast<const float4*>(
                    enc + (size_t)(bm + m) * DD + k0 + kq);
                As[kq + 0][m] = v.x; As[kq + 1][m] = v.y;
                As[kq + 2][m] = v.z; As[kq + 3][m] = v.w;
            }
#pragma unroll
            for (int t = 0; t < 2; t++) {
                int idx = tid + t * 256;
                int n   = idx >> 2;
                int kq  = (idx & 3) << 2;
                float4 v = *reinterpret_cast<const float4*>(
                    E + (size_t)(n0 + n) * DD + k0 + kq);
                Es[kq + 0][n] = v.x; Es[kq + 1][n] = v.y;
                Es[kq + 2][n] = v.z; Es[kq + 3][n] = v.w;
            }
            __syncthreads();
#pragma unroll
            for (int k = 0; k < BK; k++) {
                float a[TM], b[TN];
                *reinterpret_cast<float4*>(&a[0]) = *reinterpret_cast<float4*>(&As[k][tr * TM]);
                *reinterpret_cast<float4*>(&a[4]) = *reinterpret_cast<float4*>(&As[k][tr * TM + 4]);
                *reinterpret_cast<float4*>(&b[0]) = *reinterpret_cast<float4*>(&Es[k][tc * TN]);
                *reinterpret_cast<float4*>(&b[4]) = *reinterpret_cast<float4*>(&Es[k][tc * TN + 4]);
#pragma unroll
                for (int i = 0; i < TM; i++)
#pragma unroll
                    for (int j = 0; j < TN; j++) acc[i][j] += a[i] * b[j];
            }
            __syncthreads();
        }

#pragma unroll
        for (int j = 0; j < TN; j++) {
            int n = n0 + tc * TN + j;
            float es = __ldg(&g_esq[n]);
#pragma unroll
            for (int i = 0; i < TM; i++) {
                float v = fmaf(-2.0f, acc[i][j], es);
                if (v < bestv[i] || (v == bestv[i] && n < besti[i])) {
                    bestv[i] = v; besti[i] = n;
                }
            }
        }
    }

#pragma unroll
    for (int i = 0; i < TM; i++) {
        red_v[tr * TM + i][tc] = bestv[i];
        red_i[tr * TM + i][tc] = besti[i];
    }
    __syncthreads();
    if (tid < BM) {
        float bv = red_v[tid][0];
        int   bi = red_i[tid][0];
#pragma unroll
        for (int c = 1; c < 16; c++) {
            float v = red_v[tid][c];
            int   n = red_i[tid][c];
            if (v < bv || (v == bv && n < bi)) { bv = v; bi = n; }
        }
        g_idx[bm + tid] = bi;
    }
}

// ---------------------------------------------------------------------------
// Gather q = E[idx], accumulate sum (enc-q)^2 into g_sums[0]
// ---------------------------------------------------------------------------
__global__ void vq_gather_kernel(const float* __restrict__ enc,
                                 const float* __restrict__ E) {
    int gid    = blockIdx.x * blockDim.x + threadIdx.x;
    int stride = gridDim.x * blockDim.x;
    float local = 0.0f;
    for (int i = gid; i < BB * DD; i += stride) {
        int row = i >> 7;
        int col = i & (DD - 1);
        float e  = enc[i];
        float qq = E[((size_t)g_idx[row] << 7) + col];
        g_q[i] = qq;
        float d = e - qq;
        local += d * d;
    }
    block_reduce_add_to(local, &g_sums[0]);
}

// ---------------------------------------------------------------------------
// Head: recons = tanh(Xd @ Wh^T + bh), accumulate sum (recons-action)^2.
// 64 rows/block, 4 threads per row (4 outputs each), k chunked by 64.
// ---------------------------------------------------------------------------
__global__ __launch_bounds__(256)
void head_loss_kernel(const float* __restrict__ Xd, const float* __restrict__ Wh,
                      const float* __restrict__ bh, const float* __restrict__ action) {
    __shared__ float Ws[16][260];
    __shared__ float Xs[64][68];

    const int r0  = blockIdx.x * 64;
    const int tid = threadIdx.x;

    for (int i = tid; i < 16 * 64; i += 256) {   // 16x256 floats as float4
        int o  = i >> 6;
        int kq = (i & 63) << 2;
        float4 v = *reinterpret_cast<const float4*>(Wh + (size_t)o * HH + kq);
        Ws[o][kq] = v.x; Ws[o][kq + 1] = v.y; Ws[o][kq + 2] = v.z; Ws[o][kq + 3] = v.w;
    }

    const int row = tid >> 2;
    const int og  = (tid & 3) << 2;
    float a0 = __ldg(&bh[og + 0]), a1 = __ldg(&bh[og + 1]);
    float a2 = __ldg(&bh[og + 2]), a3 = __ldg(&bh[og + 3]);

    for (int kc = 0; kc < HH; kc += 64) {
        __syncthreads();
        for (int i = tid; i < 64 * 16; i += 256) {  // 64 rows x 16 float4
            int r  = i >> 4;
            int kq = (i & 15) << 2;
            float4 v = *reinterpret_cast<const float4*>(
                Xd + (size_t)(r0 + r) * HH + kc + kq);
            Xs[r][kq] = v.x; Xs[r][kq + 1] = v.y; Xs[r][kq + 2] = v.z; Xs[r][kq + 3] = v.w;
        }
        __syncthreads();
#pragma unroll
        for (int k = 0; k < 64; k++) {
            float x = Xs[row][k];
            a0 = fmaf(x, Ws[og + 0][kc + k], a0);
            a1 = fmaf(x, Ws[og + 1][kc + k], a1);
            a2 = fmaf(x, Ws[og + 2][kc + k], a2);
            a3 = fmaf(x, Ws[og + 3][kc + k], a3);
        }
    }

    const float* ar = action + (size_t)(r0 + row) * AA + og;
    float e = 0.0f, t;
    t = tanhf(a0) - __ldg(&ar[0]); e += t * t;
    t = tanhf(a1) - __ldg(&ar[1]); e += t * t;
    t = tanhf(a2) - __ldg(&ar[2]); e += t * t;
    t = tanhf(a3) - __ldg(&ar[3]); e += t * t;

    __syncthreads();
    block_reduce_add_to(e, &g_sums[1]);
}

// ---------------------------------------------------------------------------
// Finalize scalar
// ---------------------------------------------------------------------------
__global__ void finalize_kernel(float* __restrict__ out) {
    double vq  = g_sums[0] / ((double)BB * (double)DD);
    double rec = g_sums[1] / ((double)BB * (double)AA);
    out[0] = (float)(rec + 1.25 * vq);   // commitment*0.25 + embedding*1.0
}

// ---------------------------------------------------------------------------
// Launch
// ---------------------------------------------------------------------------
extern "C" void kernel_launch(void* const* d_in, const int* in_sizes, int n_in,
                              void* d_out, int out_size) {
    const float* action = (const float*)d_in[0];
    const float* We1    = (const float*)d_in[1];
    const float* be1    = (const float*)d_in[2];
    const float* We2    = (const float*)d_in[3];
    const float* be2    = (const float*)d_in[4];
    const float* We3    = (const float*)d_in[5];
    const float* be3    = (const float*)d_in[6];
    const float* E      = (const float*)d_in[7];
    const float* Wd1    = (const float*)d_in[8];
    const float* bd1    = (const float*)d_in[9];
    const float* Wd2    = (const float*)d_in[10];
    const float* bd2    = (const float*)d_in[11];
    const float* Wh     = (const float*)d_in[12];
    const float* bh     = (const float*)d_in[13];
    float* out = (float*)d_out;

    float* h1  = nullptr; float* h2 = nullptr; float* enc = nullptr; float* q = nullptr;
    cudaGetSymbolAddress((void**)&h1,  g_h1);
    cudaGetSymbolAddress((void**)&h2,  g_h2);
    cudaGetSymbolAddress((void**)&enc, g_enc);
    cudaGetSymbolAddress((void**)&q,   g_q);

    zero_sums_kernel<<<1, 32>>>();

    // Encoder
    gemm_bias_kernel<HH, AA, true><<<dim3(BB / 128, HH / 128), 256>>>(action, We1, be1, h1);
    gemm_bias_kernel<HH, HH, true><<<dim3(BB / 128, HH / 128), 256>>>(h1, We2, be2, h2);
    gemm_bias_kernel<DD, HH, false><<<dim3(BB / 128, DD / 128), 256>>>(h2, We3, be3, enc);

    // Codebook
    esq_kernel<<<KK / 256, 256>>>(E);
    dist_argmin_kernel<<<BB / 128, 256>>>(enc, E);
    vq_gather_kernel<<<1024, 256>>>(enc, E);

    // Decoder (q forward == straight-through value)
    gemm_bias_kernel<HH, DD, true><<<dim3(BB / 128, HH / 128), 256>>>(q, Wd1, bd1, h1);
    gemm_bias_kernel<HH, HH, true><<<dim3(BB / 128, HH / 128), 256>>>(h1, Wd2, bd2, h2);
    head_loss_kernel<<<BB / 64, 256>>>(h2, Wh, bh, action);

    finalize_kernel<<<1, 1>>>(out);
}

// round 2
// speedup vs baseline: 2.9635x; 2.9635x over previous
#include <cuda_runtime.h>
#include <cuda_bf16.h>
#include <cfloat>
#include <cstdint>

#define BB 32768
#define AA 16
#define HH 256
#define DD 128
#define KK 2048

// ---------------------------------------------------------------------------
// Scratch
// ---------------------------------------------------------------------------
__device__ float  g_h1[BB * HH];
__device__ float  g_h2[BB * HH];
__device__ float  g_enc[BB * DD];
__device__ float  g_q[BB * DD];
__device__ int    g_idx[BB];
__device__ float  g_esq[KK];
__device__ double g_sums[2];
__device__ float  g_We2r[HH * HH];
__device__ float  g_We3r[DD * HH];
__device__ float  g_Wd1r[HH * DD];
__device__ float  g_Wd2r[HH * HH];
__device__ float  g_Er[KK * DD];

// ---------------------------------------------------------------------------
// Helpers
// ---------------------------------------------------------------------------
__device__ __forceinline__ float ftf32(float x) {
    uint32_t u;
    asm("cvt.rna.tf32.f32 %0, %1;" : "=r"(u) : "f"(x));
    return __uint_as_float(u);
}

__device__ __forceinline__ unsigned su(const void* p) {
    return (unsigned)__cvta_generic_to_shared(p);
}

__device__ __forceinline__ void cp16(unsigned dst, const void* src) {
    asm volatile("cp.async.cg.shared.global [%0], [%1], 16;\n" :: "r"(dst), "l"(src));
}
__device__ __forceinline__ void cpcommit() { asm volatile("cp.async.commit_group;\n"); }
template <int N>
__device__ __forceinline__ void cpwait() { asm volatile("cp.async.wait_group %0;\n" :: "n"(N)); }

__device__ __forceinline__ void ldm4(unsigned addr, unsigned& r0, unsigned& r1,
                                     unsigned& r2, unsigned& r3) {
    asm volatile("ldmatrix.sync.aligned.m8n8.x4.shared.b16 {%0,%1,%2,%3}, [%4];\n"
                 : "=r"(r0), "=r"(r1), "=r"(r2), "=r"(r3) : "r"(addr));
}

__device__ __forceinline__ void mma_tf32(float* c, unsigned a0, unsigned a1, unsigned a2,
                                         unsigned a3, unsigned b0, unsigned b1) {
    asm volatile(
        "mma.sync.aligned.m16n8k8.row.col.f32.tf32.tf32.f32 "
        "{%0,%1,%2,%3}, {%4,%5,%6,%7}, {%8,%9}, {%0,%1,%2,%3};\n"
        : "+f"(c[0]), "+f"(c[1]), "+f"(c[2]), "+f"(c[3])
        : "r"(a0), "r"(a1), "r"(a2), "r"(a3), "r"(b0), "r"(b1));
}

__device__ __forceinline__ void block_reduce_add_to(float v, double* target) {
    __shared__ float sbuf[32];
    int lane = threadIdx.x & 31;
    int wid  = threadIdx.x >> 5;
#pragma unroll
    for (int o = 16; o; o >>= 1) v += __shfl_xor_sync(0xffffffffu, v, o);
    if (lane == 0) sbuf[wid] = v;
    __syncthreads();
    if (wid == 0) {
        int nw = blockDim.x >> 5;
        v = (lane < nw) ? sbuf[lane] : 0.0f;
#pragma unroll
        for (int o = 16; o; o >>= 1) v += __shfl_xor_sync(0xffffffffu, v, o);
        if (lane == 0) atomicAdd(target, (double)v);
    }
}

__global__ void zero_sums_kernel() {
    if (threadIdx.x < 2) g_sums[threadIdx.x] = 0.0;
}

__global__ void round4_kernel(const float4* __restrict__ src, float4* __restrict__ dst, int n4) {
    int i = blockIdx.x * blockDim.x + threadIdx.x;
    if (i < n4) {
        float4 v = src[i];
        v.x = ftf32(v.x); v.y = ftf32(v.y); v.z = ftf32(v.z); v.w = ftf32(v.w);
        dst[i] = v;
    }
}

// ---------------------------------------------------------------------------
// fp32 GEMM (layer 1 only: K=16)  Y = round_tf32(relu(X @ W^T + b))
// ---------------------------------------------------------------------------
template <int N, int K, bool RELU, bool ROUND>
__global__ __launch_bounds__(256, 2)
void gemm_bias_kernel(const float* __restrict__ X, const float* __restrict__ W,
                      const float* __restrict__ bias, float* __restrict__ Y) {
    constexpr int BM = 128, BN = 128, BK = 16, TM = 8, TN = 8;
    __shared__ float As[BK][BM];
    __shared__ float Bs[BK][BN];

    const int bm  = blockIdx.x * BM;
    const int bn  = blockIdx.y * BN;
    const int tid = threadIdx.x;
    const int tr  = tid >> 4;
    const int tc  = tid & 15;

    float acc[TM][TN];
#pragma unroll
    for (int i = 0; i < TM; i++)
#pragma unroll
        for (int j = 0; j < TN; j++) acc[i][j] = 0.0f;

    for (int k0 = 0; k0 < K; k0 += BK) {
#pragma unroll
        for (int t = 0; t < 2; t++) {
            int idx = tid + t * 256;
            int m   = idx >> 2;
            int kq  = (idx & 3) << 2;
            float4 v = *reinterpret_cast<const float4*>(X + (size_t)(bm + m) * K + k0 + kq);
            As[kq + 0][m] = v.x; As[kq + 1][m] = v.y;
            As[kq + 2][m] = v.z; As[kq + 3][m] = v.w;
        }
#pragma unroll
        for (int t = 0; t < 2; t++) {
            int idx = tid + t * 256;
            int n   = idx >> 2;
            int kq  = (idx & 3) << 2;
            float4 v = *reinterpret_cast<const float4*>(W + (size_t)(bn + n) * K + k0 + kq);
            Bs[kq + 0][n] = v.x; Bs[kq + 1][n] = v.y;
            Bs[kq + 2][n] = v.z; Bs[kq + 3][n] = v.w;
        }
        __syncthreads();
#pragma unroll
        for (int k = 0; k < BK; k++) {
            float a[TM], b[TN];
            *reinterpret_cast<float4*>(&a[0]) = *reinterpret_cast<float4*>(&As[k][tr * TM]);
            *reinterpret_cast<float4*>(&a[4]) = *reinterpret_cast<float4*>(&As[k][tr * TM + 4]);
            *reinterpret_cast<float4*>(&b[0]) = *reinterpret_cast<float4*>(&Bs[k][tc * TN]);
            *reinterpret_cast<float4*>(&b[4]) = *reinterpret_cast<float4*>(&Bs[k][tc * TN + 4]);
#pragma unroll
            for (int i = 0; i < TM; i++)
#pragma unroll
                for (int j = 0; j < TN; j++) acc[i][j] += a[i] * b[j];
        }
        __syncthreads();
    }

    float bv[TN];
#pragma unroll
    for (int j = 0; j < TN; j++) bv[j] = __ldg(&bias[bn + tc * TN + j]);

#pragma unroll
    for (int i = 0; i < TM; i++) {
        int m = bm + tr * TM + i;
#pragma unroll
        for (int j = 0; j < TN; j += 4) {
            float4 o;
            o.x = acc[i][j + 0] + bv[j + 0];
            o.y = acc[i][j + 1] + bv[j + 1];
            o.z = acc[i][j + 2] + bv[j + 2];
            o.w = acc[i][j + 3] + bv[j + 3];
            if (RELU) {
                o.x = fmaxf(o.x, 0.0f); o.y = fmaxf(o.y, 0.0f);
                o.z = fmaxf(o.z, 0.0f); o.w = fmaxf(o.w, 0.0f);
            }
            if (ROUND) {
                o.x = ftf32(o.x); o.y = ftf32(o.y); o.z = ftf32(o.z); o.w = ftf32(o.w);
            }
            *reinterpret_cast<float4*>(Y + (size_t)m * N + bn + tc * TN + j) = o;
        }
    }
}

// ---------------------------------------------------------------------------
// tf32 tensor GEMM: Y[B][N] = act(X[B][K] @ W[N][K]^T + b), operands pre-rounded
// BM=128, BN=128, BK=32, 256 threads (8 warps, warp tile 32m x 64n)
// ---------------------------------------------------------------------------
template <int N, int K, bool RELU, bool ROUND>
__global__ __launch_bounds__(256)
void tf32_gemm(const float* __restrict__ X, const float* __restrict__ W,
               const float* __restrict__ bias, float* __restrict__ Y) {
    constexpr int BM = 128, BN = 128, BK = 32;
    constexpr int NCH = K / BK;
    extern __shared__ float sm[];
    float* As = sm;                  // 2 x 128x32
    float* Bs = sm + 2 * BM * BK;    // 2 x 128x32

    const int tid = threadIdx.x;
    const int w   = tid >> 5, L = tid & 31;
    const int wm  = w & 3, wn = w >> 2;
    const int bm  = blockIdx.x * BM, bn = blockIdx.y * BN;

    const int cm = tid >> 1;
    const int ck = (tid & 1) * 4;
    const float* Xg = X + (size_t)(bm + cm) * K;
    const float* Wg = W + (size_t)(bn + cm) * K;

    float acc[2][8][4];
#pragma unroll
    for (int a = 0; a < 2; a++)
#pragma unroll
        for (int b = 0; b < 8; b++)
#pragma unroll
            for (int c = 0; c < 4; c++) acc[a][b][c] = 0.0f;

    // prefetch chunk 0
    {
        unsigned ab = su(As);
        unsigned bb = su(Bs);
#pragma unroll
        for (int i = 0; i < 4; i++) {
            int kc = ck + i;
            unsigned off = (cm * BK + ((kc ^ (cm & 7)) << 2)) * 4u;
            cp16(ab + off, Xg + kc * 4);
            cp16(bb + off, Wg + kc * 4);
        }
        cpcommit();
    }

    for (int ch = 0; ch < NCH; ch++) {
        if (ch + 1 < NCH) {
            unsigned ab = su(As + ((ch + 1) & 1) * BM * BK);
            unsigned bb = su(Bs + ((ch + 1) & 1) * BM * BK);
            int k0 = (ch + 1) * BK;
#pragma unroll
            for (int i = 0; i < 4; i++) {
                int kc = ck + i;
                unsigned off = (cm * BK + ((kc ^ (cm & 7)) << 2)) * 4u;
                cp16(ab + off, Xg + k0 + kc * 4);
                cp16(bb + off, Wg + k0 + kc * 4);
            }
            cpcommit();
            cpwait<1>();
        } else {
            cpwait<0>();
        }
        __syncthreads();

        const float* Ab = As + (ch & 1) * BM * BK;
        const float* Bb = Bs + (ch & 1) * BM * BK;

#pragma unroll
        for (int ks = 0; ks < 4; ks++) {
            unsigned a[2][4];
#pragma unroll
            for (int mt = 0; mt < 2; mt++) {
                int m  = wm * 32 + mt * 16 + (L & 15);
                int kc = ks * 2 + (L >> 4);
                ldm4(su(Ab + m * BK + ((kc ^ (m & 7)) << 2)),
                     a[mt][0], a[mt][1], a[mt][2], a[mt][3]);
            }
#pragma unroll
            for (int np = 0; np < 4; np++) {
                int n  = wn * 64 + np * 16 + ((L >> 4) << 3) + (L & 7);
                int kc = ks * 2 + ((L >> 3) & 1);
                unsigned b0, b1, b2, b3;
                ldm4(su(Bb + n * BK + ((kc ^ (n & 7)) << 2)), b0, b1, b2, b3);
#pragma unroll
                for (int mt = 0; mt < 2; mt++) {
                    mma_tf32(acc[mt][np * 2 + 0], a[mt][0], a[mt][1], a[mt][2], a[mt][3], b0, b1);
                    mma_tf32(acc[mt][np * 2 + 1], a[mt][0], a[mt][1], a[mt][2], a[mt][3], b2, b3);
                }
            }
        }
        __syncthreads();
    }

    // epilogue
    const int g = L >> 2, q4 = L & 3;
#pragma unroll
    for (int mt = 0; mt < 2; mt++) {
#pragma unroll
        for (int nt = 0; nt < 8; nt++) {
            int n = bn + wn * 64 + nt * 8 + q4 * 2;
            float b0 = __ldg(&bias[n]), b1 = __ldg(&bias[n + 1]);
#pragma unroll
            for (int h = 0; h < 2; h++) {
                int m = bm + wm * 32 + mt * 16 + g + 8 * h;
                float v0 = acc[mt][nt][2 * h + 0] + b0;
                float v1 = acc[mt][nt][2 * h + 1] + b1;
                if (RELU) { v0 = fmaxf(v0, 0.0f); v1 = fmaxf(v1, 0.0f); }
                if (ROUND) { v0 = ftf32(v0); v1 = ftf32(v1); }
                *reinterpret_cast<float2*>(Y + (size_t)m * N + n) = make_float2(v0, v1);
            }
        }
    }
}

// ---------------------------------------------------------------------------
// |E'[n]|^2 (rounded codebook)
// ---------------------------------------------------------------------------
__global__ void esq_kernel(const float* __restrict__ E) {
    int n = blockIdx.x * blockDim.x + threadIdx.x;
    if (n >= KK) return;
    const float4* r = reinterpret_cast<const float4*>(E + (size_t)n * DD);
    float s = 0.0f;
#pragma unroll
    for (int i = 0; i < DD / 4; i++) {
        float4 v = r[i];
        s += v.x * v.x + v.y * v.y + v.z * v.z + v.w * v.w;
    }
    g_esq[n] = s;
}

// ---------------------------------------------------------------------------
// tf32 dist+argmin: enc tile (128x128) resident, E streamed double-buffered.
// 512 threads: 16 warps, warp tile 32m x 32n.
// ---------------------------------------------------------------------------
__global__ __launch_bounds__(512)
void tf32_dist_argmin(const float* __restrict__ enc, const float* __restrict__ E) {
    constexpr int BM = 128, BN = 128, KD = 128;
    extern __shared__ float sm[];
    float* As    = sm;                       // 128x128
    float* Bs    = sm + BM * KD;             // 2 x 128x128
    float* s_esq = Bs + 2 * BN * KD;         // 2048
    float* red_v = s_esq + KK;               // 128*4
    int*   red_i = (int*)(red_v + 512);      // 128*4

    const int tid = threadIdx.x;
    const int w   = tid >> 5, L = tid & 31;
    const int wm  = w & 3, wn = w >> 2;      // 4 x 4 warps
    const int bm  = blockIdx.x * BM;

    // load A (enc tile) + esq, group 0 together with B tile 0
    {
        unsigned ab = su(As);
#pragma unroll
        for (int t = 0; t < 8; t++) {
            int idx = tid + t * 512;
            int m   = idx >> 5;
            int kc  = idx & 31;
            cp16(ab + (m * KD + ((kc ^ (m & 7)) << 2)) * 4u,
                 enc + (size_t)(bm + m) * KD + kc * 4);
        }
        cp16(su(s_esq) + tid * 16u, g_esq + tid * 4);
        unsigned bb = su(Bs);
#pragma unroll
        for (int t = 0; t < 8; t++) {
            int idx = tid + t * 512;
            int n   = idx >> 5;
            int kc  = idx & 31;
            cp16(bb + (n * KD + ((kc ^ (n & 7)) << 2)) * 4u,
                 E + (size_t)n * KD + kc * 4);
        }
        cpcommit();
    }

    float bestv[4];
    int   besti[4];
#pragma unroll
    for (int i = 0; i < 4; i++) { bestv[i] = FLT_MAX; besti[i] = 0; }

    const int NT = KK / BN;  // 16
    for (int t0 = 0; t0 < NT; t0++) {
        if (t0 + 1 < NT) {
            unsigned bb = su(Bs + ((t0 + 1) & 1) * BN * KD);
            const float* Eg = E + (size_t)(t0 + 1) * BN * KD;
#pragma unroll
            for (int t = 0; t < 8; t++) {
                int idx = tid + t * 512;
                int n   = idx >> 5;
                int kc  = idx & 31;
                cp16(bb + (n * KD + ((kc ^ (n & 7)) << 2)) * 4u,
                     Eg + (size_t)n * KD + kc * 4);
            }
            cpcommit();
            cpwait<1>();
        } else {
            cpwait<0>();
        }
        __syncthreads();

        const float* Bb = Bs + (t0 & 1) * BN * KD;
        float acc[2][4][4];
#pragma unroll
        for (int a = 0; a < 2; a++)
#pragma unroll
            for (int b = 0; b < 4; b++)
#pragma unroll
                for (int c = 0; c < 4; c++) acc[a][b][c] = 0.0f;

#pragma unroll
        for (int ks = 0; ks < 16; ks++) {
            unsigned a[2][4];
#pragma unroll
            for (int mt = 0; mt < 2; mt++) {
                int m  = wm * 32 + mt * 16 + (L & 15);
                int kc = ks * 2 + (L >> 4);
                ldm4(su(As + m * KD + ((kc ^ (m & 7)) << 2)),
                     a[mt][0], a[mt][1], a[mt][2], a[mt][3]);
            }
#pragma unroll
            for (int np = 0; np < 2; np++) {
                int n  = wn * 32 + np * 16 + ((L >> 4) << 3) + (L & 7);
                int kc = ks * 2 + ((L >> 3) & 1);
                unsigned b0, b1, b2, b3;
                ldm4(su(Bb + n * KD + ((kc ^ (n & 7)) << 2)), b0, b1, b2, b3);
#pragma unroll
                for (int mt = 0; mt < 2; mt++) {
                    mma_tf32(acc[mt][np * 2 + 0], a[mt][0], a[mt][1], a[mt][2], a[mt][3], b0, b1);
                    mma_tf32(acc[mt][np * 2 + 1], a[mt][0], a[mt][1], a[mt][2], a[mt][3], b2, b3);
                }
            }
        }

        // fused argmin epilogue (n ascending)
        const int q4 = L & 3;
#pragma unroll
        for (int nt = 0; nt < 4; nt++) {
            int n = t0 * BN + wn * 32 + nt * 8 + q4 * 2;
            float es0 = s_esq[n - t0 * BN + t0 * BN];  // == s_esq[n]
            float es1 = s_esq[n + 1];
            es0 = s_esq[n];
#pragma unroll
            for (int mt = 0; mt < 2; mt++) {
#pragma unroll
                for (int h = 0; h < 2; h++) {
                    int r = mt * 2 + h;
                    float v0 = fmaf(-2.0f, acc[mt][nt][2 * h + 0], es0);
                    float v1 = fmaf(-2.0f, acc[mt][nt][2 * h + 1], es1);
                    if (v0 < bestv[r]) { bestv[r] = v0; besti[r] = n; }
                    if (v1 < bestv[r]) { bestv[r] = v1; besti[r] = n + 1; }
                }
            }
        }
        __syncthreads();
    }

    // reduce across the 4 n-lanes of each row group
#pragma unroll
    for (int r = 0; r < 4; r++) {
        float v = bestv[r];
        int   ii = besti[r];
#pragma unroll
        for (int o = 1; o <= 2; o <<= 1) {
            float v2 = __shfl_xor_sync(0xffffffffu, v, o);
            int   i2 = __shfl_xor_sync(0xffffffffu, ii, o);
            if (v2 < v || (v2 == v && i2 < ii)) { v = v2; ii = i2; }
        }
        bestv[r] = v; besti[r] = ii;
    }
    if ((L & 3) == 0) {
        int g = L >> 2;
#pragma unroll
        for (int r = 0; r < 4; r++) {
            int mt = r >> 1, h = r & 1;
            int row = wm * 32 + mt * 16 + g + 8 * h;
            red_v[row * 4 + wn] = bestv[r];
            red_i[row * 4 + wn] = besti[r];
        }
    }
    __syncthreads();
    if (tid < BM) {
        float bv = red_v[tid * 4];
        int   bi = red_i[tid * 4];
#pragma unroll
        for (int c = 1; c < 4; c++) {
            float v = red_v[tid * 4 + c];
            int   n = red_i[tid * 4 + c];
            if (v < bv || (v == bv && n < bi)) { bv = v; bi = n; }
        }
        g_idx[bm + tid] = bi;
    }
}

// ---------------------------------------------------------------------------
// Gather q = E_orig[idx] (exact for vq loss), write tf32-rounded q for decoder
// ---------------------------------------------------------------------------
__global__ void vq_gather_kernel(const float* __restrict__ enc,
                                 const float* __restrict__ E) {
    int gid    = blockIdx.x * blockDim.x + threadIdx.x;
    int stride = gridDim.x * blockDim.x;
    float local = 0.0f;
    for (int i = gid; i < BB * DD; i += stride) {
        int row = i >> 7;
        int col = i & (DD - 1);
        float e  = enc[i];
        float qq = E[((size_t)g_idx[row] << 7) + col];
        g_q[i] = ftf32(qq);
        float d = e - qq;
        local += d * d;
    }
    block_reduce_add_to(local, &g_sums[0]);
}

// ---------------------------------------------------------------------------
// Head: recons = tanh(Xd @ Wh^T + bh), accumulate sum (recons-action)^2
// ---------------------------------------------------------------------------
__global__ __launch_bounds__(256)
void head_loss_kernel(const float* __restrict__ Xd, const float* __restrict__ Wh,
                      const float* __restrict__ bh, const float* __restrict__ action) {
    __shared__ float Ws[16][260];
    __shared__ float Xs[64][68];

    const int r0  = blockIdx.x * 64;
    const int tid = threadIdx.x;

    for (int i = tid; i < 16 * 64; i += 256) {
        int o  = i >> 6;
        int kq = (i & 63) << 2;
        float4 v = *reinterpret_cast<const float4*>(Wh + (size_t)o * HH + kq);
        Ws[o][kq] = v.x; Ws[o][kq + 1] = v.y; Ws[o][kq + 2] = v.z; Ws[o][kq + 3] = v.w;
    }

    const int row = tid >> 2;
    const int og  = (tid & 3) << 2;
    float a0 = __ldg(&bh[og + 0]), a1 = __ldg(&bh[og + 1]);
    float a2 = __ldg(&bh[og + 2]), a3 = __ldg(&bh[og + 3]);

    for (int kc = 0; kc < HH; kc += 64) {
        __syncthreads();
        for (int i = tid; i < 64 * 16; i += 256) {
            int r  = i >> 4;
            int kq = (i & 15) << 2;
            float4 v = *reinterpret_cast<const float4*>(Xd + (size_t)(r0 + r) * HH + kc + kq);
            Xs[r][kq] = v.x; Xs[r][kq + 1] = v.y; Xs[r][kq + 2] = v.z; Xs[r][kq + 3] = v.w;
        }
        __syncthreads();
#pragma unroll
        for (int k = 0; k < 64; k++) {
            float x = Xs[row][k];
            a0 = fmaf(x, Ws[og + 0][kc + k], a0);
            a1 = fmaf(x, Ws[og + 1][kc + k], a1);
            a2 = fmaf(x, Ws[og + 2][kc + k], a2);
            a3 = fmaf(x, Ws[og + 3][kc + k], a3);
        }
    }

    const float* ar = action + (size_t)(r0 + row) * AA + og;
    float e = 0.0f, t;
    t = tanhf(a0) - __ldg(&ar[0]); e += t * t;
    t = tanhf(a1) - __ldg(&ar[1]); e += t * t;
    t = tanhf(a2) - __ldg(&ar[2]); e += t * t;
    t = tanhf(a3) - __ldg(&ar[3]); e += t * t;

    __syncthreads();
    block_reduce_add_to(e, &g_sums[1]);
}

__global__ void finalize_kernel(float* __restrict__ out) {
    double vq  = g_sums[0] / ((double)BB * (double)DD);
    double rec = g_sums[1] / ((double)BB * (double)AA);
    out[0] = (float)(rec + 1.25 * vq);
}

// ---------------------------------------------------------------------------
// Launch
// ---------------------------------------------------------------------------
extern "C" void kernel_launch(void* const* d_in, const int* in_sizes, int n_in,
                              void* d_out, int out_size) {
    const float* action = (const float*)d_in[0];
    const float* We1    = (const float*)d_in[1];
    const float* be1    = (const float*)d_in[2];
    const float* We2    = (const float*)d_in[3];
    const float* be2    = (const float*)d_in[4];
    const float* We3    = (const float*)d_in[5];
    const float* be3    = (const float*)d_in[6];
    const float* E      = (const float*)d_in[7];
    const float* Wd1    = (const float*)d_in[8];
    const float* bd1    = (const float*)d_in[9];
    const float* Wd2    = (const float*)d_in[10];
    const float* bd2    = (const float*)d_in[11];
    const float* Wh     = (const float*)d_in[12];
    const float* bh     = (const float*)d_in[13];
    float* out = (float*)d_out;

    float *h1, *h2, *enc, *q, *We2r, *We3r, *Wd1r, *Wd2r, *Er;
    cudaGetSymbolAddress((void**)&h1,   g_h1);
    cudaGetSymbolAddress((void**)&h2,   g_h2);
    cudaGetSymbolAddress((void**)&enc,  g_enc);
    cudaGetSymbolAddress((void**)&q,    g_q);
    cudaGetSymbolAddress((void**)&We2r, g_We2r);
    cudaGetSymbolAddress((void**)&We3r, g_We3r);
    cudaGetSymbolAddress((void**)&Wd1r, g_Wd1r);
    cudaGetSymbolAddress((void**)&Wd2r, g_Wd2r);
    cudaGetSymbolAddress((void**)&Er,   g_Er);

    const int GEMM_SMEM = 2 * 128 * 32 * 2 * sizeof(float);                 // 65536
    const int DIST_SMEM = (128 * 128 + 2 * 128 * 128 + KK + 1024) * 4;      // 208896
    cudaFuncSetAttribute((const void*)tf32_gemm<HH, HH, true,  true>,
                         cudaFuncAttributeMaxDynamicSharedMemorySize, GEMM_SMEM);
    cudaFuncSetAttribute((const void*)tf32_gemm<DD, HH, false, true>,
                         cudaFuncAttributeMaxDynamicSharedMemorySize, GEMM_SMEM);
    cudaFuncSetAttribute((const void*)tf32_gemm<HH, DD, true,  true>,
                         cudaFuncAttributeMaxDynamicSharedMemorySize, GEMM_SMEM);
    cudaFuncSetAttribute((const void*)tf32_gemm<HH, HH, true,  false>,
                         cudaFuncAttributeMaxDynamicSharedMemorySize, GEMM_SMEM);
    cudaFuncSetAttribute((const void*)tf32_dist_argmin,
                         cudaFuncAttributeMaxDynamicSharedMemorySize, DIST_SMEM);

    zero_sums_kernel<<<1, 32>>>();

    // round weights / codebook to tf32 once per call
    round4_kernel<<<(HH * HH / 4 + 255) / 256, 256>>>((const float4*)We2, (float4*)We2r, HH * HH / 4);
    round4_kernel<<<(DD * HH / 4 + 255) / 256, 256>>>((const float4*)We3, (float4*)We3r, DD * HH / 4);
    round4_kernel<<<(HH * DD / 4 + 255) / 256, 256>>>((const float4*)Wd1, (float4*)Wd1r, HH * DD / 4);
    round4_kernel<<<(HH * HH / 4 + 255) / 256, 256>>>((const float4*)Wd2, (float4*)Wd2r, HH * HH / 4);
    round4_kernel<<<(KK * DD / 4 + 255) / 256, 256>>>((const float4*)E,   (float4*)Er,   KK * DD / 4);
    esq_kernel<<<KK / 256, 256>>>(Er);

    // encoder
    gemm_bias_kernel<HH, AA, true, true><<<dim3(BB / 128, HH / 128), 256>>>(action, We1, be1, h1);
    tf32_gemm<HH, HH, true,  true><<<dim3(BB / 128, HH / 128), 256, GEMM_SMEM>>>(h1, We2r, be2, h2);
    tf32_gemm<DD, HH, false, true><<<dim3(BB / 128, DD / 128), 256, GEMM_SMEM>>>(h2, We3r, be3, enc);

    // codebook
    tf32_dist_argmin<<<BB / 128, 512, DIST_SMEM>>>(enc, Er);
    vq_gather_kernel<<<1024, 256>>>(enc, E);

    // decoder
    tf32_gemm<HH, DD, true, true ><<<dim3(BB / 128, HH / 128), 256, GEMM_SMEM>>>(q, Wd1r, bd1, h1);
    tf32_gemm<HH, HH, true, false><<<dim3(BB / 128, HH / 128), 256, GEMM_SMEM>>>(h1, Wd2r, bd2, h2);
    head_loss_kernel<<<BB / 64, 256>>>(h2, Wh, bh, action);

    finalize_kernel<<<1, 1>>>(out);
}

// round 3
// speedup vs baseline: 4.7198x; 1.5927x over previous
#include <cuda_runtime.h>
#include <cuda_bf16.h>
#include <cfloat>
#include <cstdint>

#define BB 32768
#define AA 16
#define HH 256
#define DD 128
#define KK 2048

// ---------------------------------------------------------------------------
// Scratch (device globals)
// ---------------------------------------------------------------------------
__device__ __nv_bfloat16 g_h1b[BB * HH];
__device__ __nv_bfloat16 g_h2b[BB * HH];
__device__ __nv_bfloat16 g_encb[BB * DD];
__device__ __nv_bfloat16 g_qb[BB * DD];
__device__ __nv_bfloat16 g_We2b[HH * HH];
__device__ __nv_bfloat16 g_We3b[DD * HH];
__device__ __nv_bfloat16 g_Wd1b[HH * DD];
__device__ __nv_bfloat16 g_Wd2b[HH * HH];
__device__ __nv_bfloat16 g_Eb[KK * DD];
__device__ int    g_idx[BB];
__device__ float  g_esq[KK];
__device__ double g_sums[2];

// ---------------------------------------------------------------------------
// Helpers
// ---------------------------------------------------------------------------
__device__ __forceinline__ unsigned su(const void* p) {
    return (unsigned)__cvta_generic_to_shared(p);
}
__device__ __forceinline__ void cp16(unsigned dst, const void* src) {
    asm volatile("cp.async.cg.shared.global [%0], [%1], 16;\n" :: "r"(dst), "l"(src));
}
__device__ __forceinline__ void cpcommit() { asm volatile("cp.async.commit_group;\n"); }
template <int N>
__device__ __forceinline__ void cpwait() { asm volatile("cp.async.wait_group %0;\n" :: "n"(N)); }

__device__ __forceinline__ void ldm4(unsigned addr, unsigned& r0, unsigned& r1,
                                     unsigned& r2, unsigned& r3) {
    asm volatile("ldmatrix.sync.aligned.m8n8.x4.shared.b16 {%0,%1,%2,%3}, [%4];\n"
                 : "=r"(r0), "=r"(r1), "=r"(r2), "=r"(r3) : "r"(addr));
}
__device__ __forceinline__ void mma_bf16(float* c, unsigned a0, unsigned a1, unsigned a2,
                                         unsigned a3, unsigned b0, unsigned b1) {
    asm volatile(
        "mma.sync.aligned.m16n8k16.row.col.f32.bf16.bf16.f32 "
        "{%0,%1,%2,%3}, {%4,%5,%6,%7}, {%8,%9}, {%0,%1,%2,%3};\n"
        : "+f"(c[0]), "+f"(c[1]), "+f"(c[2]), "+f"(c[3])
        : "r"(a0), "r"(a1), "r"(a2), "r"(a3), "r"(b0), "r"(b1));
}

__device__ __forceinline__ void block_reduce_add_to(float v, double* target) {
    __shared__ float sbuf[32];
    int lane = threadIdx.x & 31;
    int wid  = threadIdx.x >> 5;
#pragma unroll
    for (int o = 16; o; o >>= 1) v += __shfl_xor_sync(0xffffffffu, v, o);
    if (lane == 0) sbuf[wid] = v;
    __syncthreads();
    if (wid == 0) {
        int nw = blockDim.x >> 5;
        v = (lane < nw) ? sbuf[lane] : 0.0f;
#pragma unroll
        for (int o = 16; o; o >>= 1) v += __shfl_xor_sync(0xffffffffu, v, o);
        if (lane == 0) atomicAdd(target, (double)v);
    }
}

__global__ void zero_sums_kernel() {
    if (threadIdx.x < 2) g_sums[threadIdx.x] = 0.0;
}

// ---------------------------------------------------------------------------
// Convert all weights + codebook fp32 -> bf16 in one kernel.
// Segments (float4 units): We2 16384 | We3 8192 | Wd1 8192 | Wd2 16384 | E 65536
// ---------------------------------------------------------------------------
__global__ void convert_all_kernel(const float4* __restrict__ We2, const float4* __restrict__ We3,
                                   const float4* __restrict__ Wd1, const float4* __restrict__ Wd2,
                                   const float4* __restrict__ E) {
    int i = blockIdx.x * 256 + threadIdx.x;   // 0..114687
    const float4* src; uint2* dst; int j;
    if (i < 16384)       { src = We2; dst = (uint2*)g_We2b; j = i; }
    else if (i < 24576)  { src = We3; dst = (uint2*)g_We3b; j = i - 16384; }
    else if (i < 32768)  { src = Wd1; dst = (uint2*)g_Wd1b; j = i - 24576; }
    else if (i < 49152)  { src = Wd2; dst = (uint2*)g_Wd2b; j = i - 32768; }
    else                 { src = E;   dst = (uint2*)g_Eb;   j = i - 49152; }
    float4 v = src[j];
    __nv_bfloat162 h0 = __floats2bfloat162_rn(v.x, v.y);
    __nv_bfloat162 h1 = __floats2bfloat162_rn(v.z, v.w);
    uint2 p;
    p.x = *reinterpret_cast<unsigned*>(&h0);
    p.y = *reinterpret_cast<unsigned*>(&h1);
    dst[j] = p;
}

// |E_bf[n]|^2 in fp32 (consistent with bf16 mma operands)
__global__ void esq_bf_kernel() {
    int n = blockIdx.x * 256 + threadIdx.x;
    if (n >= KK) return;
    const uint4* p = reinterpret_cast<const uint4*>(g_Eb + (size_t)n * DD);
    float s = 0.0f;
#pragma unroll
    for (int i = 0; i < DD / 8; i++) {
        uint4 r = p[i];
        const __nv_bfloat162* h = reinterpret_cast<const __nv_bfloat162*>(&r);
#pragma unroll
        for (int j = 0; j < 4; j++) {
            float2 f = __bfloat1622float2(h[j]);
            s += f.x * f.x + f.y * f.y;
        }
    }
    g_esq[n] = s;
}

// ---------------------------------------------------------------------------
// Layer 1 (fp32 in, K=16): h1 = bf16(relu(action @ We1^T + be1))
// ---------------------------------------------------------------------------
__global__ __launch_bounds__(256, 2)
void layer1_kernel(const float* __restrict__ X, const float* __restrict__ W,
                   const float* __restrict__ bias, __nv_bfloat16* __restrict__ Y) {
    constexpr int N = HH, K = AA, BM = 128, BN = 128, TM = 8, TN = 8;
    __shared__ float As[K][BM];
    __shared__ float Bs[K][BN];

    const int bm  = blockIdx.x * BM;
    const int bn  = blockIdx.y * BN;
    const int tid = threadIdx.x;
    const int tr  = tid >> 4;
    const int tc  = tid & 15;

    {
#pragma unroll
        for (int t = 0; t < 2; t++) {
            int idx = tid + t * 256;
            int m   = idx >> 2;
            int kq  = (idx & 3) << 2;
            float4 v = *reinterpret_cast<const float4*>(X + (size_t)(bm + m) * K + kq);
            As[kq + 0][m] = v.x; As[kq + 1][m] = v.y;
            As[kq + 2][m] = v.z; As[kq + 3][m] = v.w;
        }
#pragma unroll
        for (int t = 0; t < 2; t++) {
            int idx = tid + t * 256;
            int n   = idx >> 2;
            int kq  = (idx & 3) << 2;
            float4 v = *reinterpret_cast<const float4*>(W + (size_t)(bn + n) * K + kq);
            Bs[kq + 0][n] = v.x; Bs[kq + 1][n] = v.y;
            Bs[kq + 2][n] = v.z; Bs[kq + 3][n] = v.w;
        }
        __syncthreads();
    }

    float acc[TM][TN];
#pragma unroll
    for (int i = 0; i < TM; i++)
#pragma unroll
        for (int j = 0; j < TN; j++) acc[i][j] = 0.0f;

#pragma unroll
    for (int k = 0; k < K; k++) {
        float a[TM], b[TN];
        *reinterpret_cast<float4*>(&a[0]) = *reinterpret_cast<float4*>(&As[k][tr * TM]);
        *reinterpret_cast<float4*>(&a[4]) = *reinterpret_cast<float4*>(&As[k][tr * TM + 4]);
        *reinterpret_cast<float4*>(&b[0]) = *reinterpret_cast<float4*>(&Bs[k][tc * TN]);
        *reinterpret_cast<float4*>(&b[4]) = *reinterpret_cast<float4*>(&Bs[k][tc * TN + 4]);
#pragma unroll
        for (int i = 0; i < TM; i++)
#pragma unroll
            for (int j = 0; j < TN; j++) acc[i][j] += a[i] * b[j];
    }

    float bv[TN];
#pragma unroll
    for (int j = 0; j < TN; j++) bv[j] = __ldg(&bias[bn + tc * TN + j]);

#pragma unroll
    for (int i = 0; i < TM; i++) {
        int m = bm + tr * TM + i;
#pragma unroll
        for (int j = 0; j < TN; j += 4) {
            float v0 = fmaxf(acc[i][j + 0] + bv[j + 0], 0.0f);
            float v1 = fmaxf(acc[i][j + 1] + bv[j + 1], 0.0f);
            float v2 = fmaxf(acc[i][j + 2] + bv[j + 2], 0.0f);
            float v3 = fmaxf(acc[i][j + 3] + bv[j + 3], 0.0f);
            __nv_bfloat162 h0 = __floats2bfloat162_rn(v0, v1);
            __nv_bfloat162 h1 = __floats2bfloat162_rn(v2, v3);
            uint2 p;
            p.x = *reinterpret_cast<unsigned*>(&h0);
            p.y = *reinterpret_cast<unsigned*>(&h1);
            *reinterpret_cast<uint2*>(Y + (size_t)m * N + bn + tc * TN + j) = p;
        }
    }
}

// ---------------------------------------------------------------------------
// bf16 tensor GEMM: Y[B][N] = act(X[B][K] @ W[N][K]^T + b)
// BM=128, BN=128, BK=64 (bf16), 256 threads (8 warps, warp tile 32m x 64n)
// ---------------------------------------------------------------------------
template <int N, int K, bool RELU>
__global__ __launch_bounds__(256, 2)
void bf16_gemm(const __nv_bfloat16* __restrict__ X, const __nv_bfloat16* __restrict__ W,
               const float* __restrict__ bias, __nv_bfloat16* __restrict__ Y) {
    constexpr int BM = 128, BN = 128, BK = 64;
    constexpr int NCH = K / BK;
    extern __shared__ __nv_bfloat16 smb[];
    __nv_bfloat16* As = smb;                    // 2 x 128x64
    __nv_bfloat16* Bs = smb + 2 * BM * BK;      // 2 x 128x64

    const int tid = threadIdx.x;
    const int w   = tid >> 5, L = tid & 31;
    const int wm  = w & 3, wn = w >> 2;
    const int bm  = blockIdx.x * BM, bn = blockIdx.y * BN;

    const int cm = tid >> 1;            // row 0..127
    const int cb = (tid & 1) * 4;       // chunk base
    const __nv_bfloat16* Xg = X + (size_t)(bm + cm) * K;
    const __nv_bfloat16* Wg = W + (size_t)(bn + cm) * K;

    float acc[2][8][4];
#pragma unroll
    for (int a = 0; a < 2; a++)
#pragma unroll
        for (int b = 0; b < 8; b++)
#pragma unroll
            for (int c = 0; c < 4; c++) acc[a][b][c] = 0.0f;

    unsigned abase = su(As), bbase = su(Bs);

    {
#pragma unroll
        for (int i = 0; i < 4; i++) {
            int c = cb + i;
            unsigned off = (cm * 8 + (c ^ (cm & 7))) * 16u;
            cp16(abase + off, Xg + c * 8);
            cp16(bbase + off, Wg + c * 8);
        }
        cpcommit();
    }

    for (int ch = 0; ch < NCH; ch++) {
        if (ch + 1 < NCH) {
            unsigned ab = abase + ((ch + 1) & 1) * (BM * BK * 2);
            unsigned bb = bbase + ((ch + 1) & 1) * (BM * BK * 2);
            int k0 = (ch + 1) * BK;
#pragma unroll
            for (int i = 0; i < 4; i++) {
                int c = cb + i;
                unsigned off = (cm * 8 + (c ^ (cm & 7))) * 16u;
                cp16(ab + off, Xg + k0 + c * 8);
                cp16(bb + off, Wg + k0 + c * 8);
            }
            cpcommit();
            cpwait<1>();
        } else {
            cpwait<0>();
        }
        __syncthreads();

        unsigned Ab = abase + (ch & 1) * (BM * BK * 2);
        unsigned Bb = bbase + (ch & 1) * (BM * BK * 2);

#pragma unroll
        for (int ks = 0; ks < 4; ks++) {
            unsigned a[2][4];
#pragma unroll
            for (int mt = 0; mt < 2; mt++) {
                int m  = wm * 32 + mt * 16 + (L & 15);
                int ck = ks * 2 + (L >> 4);
                ldm4(Ab + (m * 8 + (ck ^ (m & 7))) * 16u,
                     a[mt][0], a[mt][1], a[mt][2], a[mt][3]);
            }
#pragma unroll
            for (int np = 0; np < 4; np++) {
                int n  = wn * 64 + np * 16 + (L & 7) + ((L >> 4) << 3);
                int ck = ks * 2 + ((L >> 3) & 1);
                unsigned b0, b1, b2, b3;
                ldm4(Bb + (n * 8 + (ck ^ (n & 7))) * 16u, b0, b1, b2, b3);
#pragma unroll
                for (int mt = 0; mt < 2; mt++) {
                    mma_bf16(acc[mt][np * 2 + 0], a[mt][0], a[mt][1], a[mt][2], a[mt][3], b0, b1);
                    mma_bf16(acc[mt][np * 2 + 1], a[mt][0], a[mt][1], a[mt][2], a[mt][3], b2, b3);
                }
            }
        }
        __syncthreads();
    }

    const int g = L >> 2, q2 = (L & 3) * 2;
#pragma unroll
    for (int mt = 0; mt < 2; mt++) {
#pragma unroll
        for (int nt = 0; nt < 8; nt++) {
            int n = bn + wn * 64 + nt * 8 + q2;
            float b0 = __ldg(&bias[n]), b1 = __ldg(&bias[n + 1]);
#pragma unroll
            for (int h = 0; h < 2; h++) {
                int m = bm + wm * 32 + mt * 16 + g + 8 * h;
                float v0 = acc[mt][nt][2 * h + 0] + b0;
                float v1 = acc[mt][nt][2 * h + 1] + b1;
                if (RELU) { v0 = fmaxf(v0, 0.0f); v1 = fmaxf(v1, 0.0f); }
                __nv_bfloat162 hv = __floats2bfloat162_rn(v0, v1);
                *reinterpret_cast<__nv_bfloat162*>(Y + (size_t)m * N + n) = hv;
            }
        }
    }
}

// ---------------------------------------------------------------------------
// bf16 dist+argmin: BM=256 rows/block (grid 128 = one wave), enc tile resident,
// E streamed double-buffered. 512 threads: 16 warps (4m x 4n), warp 64m x 32n.
// d2' = |E[n]|^2 - 2*enc.E[n]
// ---------------------------------------------------------------------------
__global__ __launch_bounds__(512, 1)
void bf16_dist_argmin(const __nv_bfloat16* __restrict__ enc,
                      const __nv_bfloat16* __restrict__ Eb) {
    constexpr int BM = 256, BN = 128, KD = 128;
    extern __shared__ unsigned char smraw[];
    __nv_bfloat16* As = (__nv_bfloat16*)smraw;        // 256x128 bf16 = 64KB
    __nv_bfloat16* Bs = As + BM * KD;                 // 2 x 128x128 bf16 = 64KB
    float* s_esq = (float*)(Bs + 2 * BN * KD);        // 8KB
    float* red_v = s_esq + KK;                        // 256*4 f32
    int*   red_i = (int*)(red_v + BM * 4);            // 256*4 i32

    const int tid = threadIdx.x;
    const int w   = tid >> 5, L = tid & 31;
    const int wm  = w & 3, wn = w >> 2;
    const int bm  = blockIdx.x * BM;

    unsigned abase = su(As), bbase = su(Bs);

    // group 0: A tile (256x16 chunks), esq, B tile 0
    {
#pragma unroll
        for (int t = 0; t < 8; t++) {
            int idx = tid + t * 512;
            int m   = idx >> 4;
            int c   = idx & 15;
            int sw  = (c & 8) | ((c & 7) ^ (m & 7));
            cp16(abase + (m * 16 + sw) * 16u, enc + (size_t)(bm + m) * KD + c * 8);
        }
        cp16(su(s_esq) + tid * 16u, g_esq + tid * 4);
#pragma unroll
        for (int t = 0; t < 4; t++) {
            int idx = tid + t * 512;
            int n   = idx >> 4;
            int c   = idx & 15;
            int sw  = (c & 8) | ((c & 7) ^ (n & 7));
            cp16(bbase + (n * 16 + sw) * 16u, Eb + (size_t)n * KD + c * 8);
        }
        cpcommit();
    }

    float bestv[8];
    int   besti[8];
#pragma unroll
    for (int i = 0; i < 8; i++) { bestv[i] = FLT_MAX; besti[i] = 0; }

    const int NT = KK / BN;  // 16
    for (int t0 = 0; t0 < NT; t0++) {
        if (t0 + 1 < NT) {
            unsigned bb = bbase + ((t0 + 1) & 1) * (BN * KD * 2);
            const __nv_bfloat16* Eg = Eb + (size_t)(t0 + 1) * BN * KD;
#pragma unroll
            for (int t = 0; t < 4; t++) {
                int idx = tid + t * 512;
                int n   = idx >> 4;
                int c   = idx & 15;
                int sw  = (c & 8) | ((c & 7) ^ (n & 7));
                cp16(bb + (n * 16 + sw) * 16u, Eg + (size_t)n * KD + c * 8);
            }
            cpcommit();
            cpwait<1>();
        } else {
            cpwait<0>();
        }
        __syncthreads();

        unsigned Bb = bbase + (t0 & 1) * (BN * KD * 2);

        float acc[4][4][4];
#pragma unroll
        for (int a = 0; a < 4; a++)
#pragma unroll
            for (int b = 0; b < 4; b++)
#pragma unroll
                for (int c = 0; c < 4; c++) acc[a][b][c] = 0.0f;

#pragma unroll
        for (int ks = 0; ks < 8; ks++) {
            unsigned a[4][4];
#pragma unroll
            for (int mt = 0; mt < 4; mt++) {
                int m  = wm * 64 + mt * 16 + (L & 15);
                int ck = ks * 2 + (L >> 4);
                int sw = (ck & 8) | ((ck & 7) ^ (m & 7));
                ldm4(abase + (m * 16 + sw) * 16u, a[mt][0], a[mt][1], a[mt][2], a[mt][3]);
            }
#pragma unroll
            for (int np = 0; np < 2; np++) {
                int n  = wn * 32 + np * 16 + (L & 7) + ((L >> 4) << 3);
                int ck = ks * 2 + ((L >> 3) & 1);
                int sw = (ck & 8) | ((ck & 7) ^ (n & 7));
                unsigned b0, b1, b2, b3;
                ldm4(Bb + (n * 16 + sw) * 16u, b0, b1, b2, b3);
#pragma unroll
                for (int mt = 0; mt < 4; mt++) {
                    mma_bf16(acc[mt][np * 2 + 0], a[mt][0], a[mt][1], a[mt][2], a[mt][3], b0, b1);
                    mma_bf16(acc[mt][np * 2 + 1], a[mt][0], a[mt][1], a[mt][2], a[mt][3], b2, b3);
                }
            }
        }

        // fused argmin epilogue
        const int q2 = (L & 3) * 2;
#pragma unroll
        for (int nj = 0; nj < 4; nj++) {
            int n = t0 * BN + wn * 32 + nj * 8 + q2;
            float es0 = s_esq[n];
            float es1 = s_esq[n + 1];
#pragma unroll
            for (int mt = 0; mt < 4; mt++) {
#pragma unroll
                for (int h = 0; h < 2; h++) {
                    int r = mt * 2 + h;
                    float v0 = fmaf(-2.0f, acc[mt][nj][2 * h + 0], es0);
                    float v1 = fmaf(-2.0f, acc[mt][nj][2 * h + 1], es1);
                    if (v0 < bestv[r]) { bestv[r] = v0; besti[r] = n; }
                    if (v1 < bestv[r]) { bestv[r] = v1; besti[r] = n + 1; }
                }
            }
        }
        __syncthreads();
    }

    // reduce across quad lanes (the 4 n-columns inside the fragment)
#pragma unroll
    for (int r = 0; r < 8; r++) {
        float v = bestv[r];
        int   ii = besti[r];
#pragma unroll
        for (int o = 1; o <= 2; o <<= 1) {
            float v2 = __shfl_xor_sync(0xffffffffu, v, o);
            int   i2 = __shfl_xor_sync(0xffffffffu, ii, o);
            if (v2 < v || (v2 == v && i2 < ii)) { v = v2; ii = i2; }
        }
        bestv[r] = v; besti[r] = ii;
    }
    if ((L & 3) == 0) {
        int g = L >> 2;
#pragma unroll
        for (int r = 0; r < 8; r++) {
            int mt = r >> 1, h = r & 1;
            int row = wm * 64 + mt * 16 + g + 8 * h;
            red_v[row * 4 + wn] = bestv[r];
            red_i[row * 4 + wn] = besti[r];
        }
    }
    __syncthreads();
    if (tid < BM) {
        float bv = red_v[tid * 4];
        int   bi = red_i[tid * 4];
#pragma unroll
        for (int c = 1; c < 4; c++) {
            float v = red_v[tid * 4 + c];
            int   n = red_i[tid * 4 + c];
            if (v < bv || (v == bv && n < bi)) { bv = v; bi = n; }
        }
        g_idx[bm + tid] = bi;
    }
}

// ---------------------------------------------------------------------------
// Gather q = E_fp32[idx]; vq sum (enc_bf - q)^2; store q as bf16 for decoder.
// 8 elements per thread.
// ---------------------------------------------------------------------------
__global__ void vq_gather_kernel(const __nv_bfloat16* __restrict__ enc,
                                 const float* __restrict__ E,
                                 __nv_bfloat16* __restrict__ q) {
    int i   = blockIdx.x * 256 + threadIdx.x;      // 0 .. BB*DD/8-1
    int row = i >> 4;
    int c   = (i & 15) << 3;
    int code = g_idx[row];
    const float4* Ep = reinterpret_cast<const float4*>(E + ((size_t)code << 7) + c);
    float4 q0 = Ep[0], q1 = Ep[1];
    uint4 ev = *reinterpret_cast<const uint4*>(enc + ((size_t)row << 7) + c);
    const __nv_bfloat162* eh = reinterpret_cast<const __nv_bfloat162*>(&ev);
    float2 e0 = __bfloat1622float2(eh[0]);
    float2 e1 = __bfloat1622float2(eh[1]);
    float2 e2 = __bfloat1622float2(eh[2]);
    float2 e3 = __bfloat1622float2(eh[3]);
    float s = 0.0f, d;
    d = e0.x - q0.x; s += d * d;  d = e0.y - q0.y; s += d * d;
    d = e1.x - q0.z; s += d * d;  d = e1.y - q0.w; s += d * d;
    d = e2.x - q1.x; s += d * d;  d = e2.y - q1.y; s += d * d;
    d = e3.x - q1.z; s += d * d;  d = e3.y - q1.w; s += d * d;
    uint4 outv;
    __nv_bfloat162 h;
    h = __floats2bfloat162_rn(q0.x, q0.y); outv.x = *reinterpret_cast<unsigned*>(&h);
    h = __floats2bfloat162_rn(q0.z, q0.w); outv.y = *reinterpret_cast<unsigned*>(&h);
    h = __floats2bfloat162_rn(q1.x, q1.y); outv.z = *reinterpret_cast<unsigned*>(&h);
    h = __floats2bfloat162_rn(q1.z, q1.w); outv.w = *reinterpret_cast<unsigned*>(&h);
    *reinterpret_cast<uint4*>(q + ((size_t)row << 7) + c) = outv;
    block_reduce_add_to(s, &g_sums[0]);
}

// ---------------------------------------------------------------------------
// Head: recons = tanh(Xd @ Wh^T + bh) vs action, sum of squares.
// Xd is bf16 [B][256], Wh fp32 [16][256].
// ---------------------------------------------------------------------------
__global__ __launch_bounds__(256)
void head_loss_kernel(const __nv_bfloat16* __restrict__ Xd, const float* __restrict__ Wh,
                      const float* __restrict__ bh, const float* __restrict__ action) {
    __shared__ float Ws[16][260];
    __shared__ float Xs[64][68];

    const int r0  = blockIdx.x * 64;
    const int tid = threadIdx.x;

    for (int i = tid; i < 16 * 64; i += 256) {
        int o  = i >> 6;
        int kq = (i & 63) << 2;
        float4 v = *reinterpret_cast<const float4*>(Wh + (size_t)o * HH + kq);
        Ws[o][kq] = v.x; Ws[o][kq + 1] = v.y; Ws[o][kq + 2] = v.z; Ws[o][kq + 3] = v.w;
    }

    const int row = tid >> 2;
    const int og  = (tid & 3) << 2;
    float a0 = __ldg(&bh[og + 0]), a1 = __ldg(&bh[og + 1]);
    float a2 = __ldg(&bh[og + 2]), a3 = __ldg(&bh[og + 3]);

    for (int kc = 0; kc < HH; kc += 64) {
        __syncthreads();
        for (int i = tid; i < 64 * 8; i += 256) {     // 512 x uint4 (8 bf16)
            int r  = i >> 3;
            int c8 = (i & 7) << 3;
            uint4 raw = *reinterpret_cast<const uint4*>(
                Xd + (size_t)(r0 + r) * HH + kc + c8);
            const __nv_bfloat162* h = reinterpret_cast<const __nv_bfloat162*>(&raw);
            float* xs = &Xs[r][c8];
#pragma unroll
            for (int j = 0; j < 4; j++) {
                float2 f = __bfloat1622float2(h[j]);
                xs[2 * j] = f.x; xs[2 * j + 1] = f.y;
            }
        }
        __syncthreads();
#pragma unroll
        for (int k = 0; k < 64; k++) {
            float x = Xs[row][k];
            a0 = fmaf(x, Ws[og + 0][kc + k], a0);
            a1 = fmaf(x, Ws[og + 1][kc + k], a1);
            a2 = fmaf(x, Ws[og + 2][kc + k], a2);
            a3 = fmaf(x, Ws[og + 3][kc + k], a3);
        }
    }

    const float* ar = action + (size_t)(r0 + row) * AA + og;
    float e = 0.0f, t;
    t = tanhf(a0) - __ldg(&ar[0]); e += t * t;
    t = tanhf(a1) - __ldg(&ar[1]); e += t * t;
    t = tanhf(a2) - __ldg(&ar[2]); e += t * t;
    t = tanhf(a3) - __ldg(&ar[3]); e += t * t;

    __syncthreads();
    block_reduce_add_to(e, &g_sums[1]);
}

__global__ void finalize_kernel(float* __restrict__ out) {
    double vq  = g_sums[0] / ((double)BB * (double)DD);
    double rec = g_sums[1] / ((double)BB * (double)AA);
    out[0] = (float)(rec + 1.25 * vq);
}

// ---------------------------------------------------------------------------
// Launch
// ---------------------------------------------------------------------------
extern "C" void kernel_launch(void* const* d_in, const int* in_sizes, int n_in,
                              void* d_out, int out_size) {
    const float* action = (const float*)d_in[0];
    const float* We1    = (const float*)d_in[1];
    const float* be1    = (const float*)d_in[2];
    const float* We2    = (const float*)d_in[3];
    const float* be2    = (const float*)d_in[4];
    const float* We3    = (const float*)d_in[5];
    const float* be3    = (const float*)d_in[6];
    const float* E      = (const float*)d_in[7];
    const float* Wd1    = (const float*)d_in[8];
    const float* bd1    = (const float*)d_in[9];
    const float* Wd2    = (const float*)d_in[10];
    const float* bd2    = (const float*)d_in[11];
    const float* Wh     = (const float*)d_in[12];
    const float* bh     = (const float*)d_in[13];
    float* out = (float*)d_out;

    __nv_bfloat16 *h1, *h2, *enc, *q, *We2b, *We3b, *Wd1b, *Wd2b, *Eb;
    cudaGetSymbolAddress((void**)&h1,   g_h1b);
    cudaGetSymbolAddress((void**)&h2,   g_h2b);
    cudaGetSymbolAddress((void**)&enc,  g_encb);
    cudaGetSymbolAddress((void**)&q,    g_qb);
    cudaGetSymbolAddress((void**)&We2b, g_We2b);
    cudaGetSymbolAddress((void**)&We3b, g_We3b);
    cudaGetSymbolAddress((void**)&Wd1b, g_Wd1b);
    cudaGetSymbolAddress((void**)&Wd2b, g_Wd2b);
    cudaGetSymbolAddress((void**)&Eb,   g_Eb);

    const int GEMM_SMEM = 2 * 128 * 64 * 2 * 2;                 // 65536 B
    const int DIST_SMEM = 256 * 128 * 2 + 2 * 128 * 128 * 2 +
                          KK * 4 + 256 * 4 * 4 + 256 * 4 * 4;   // 147456 B
    cudaFuncSetAttribute((const void*)bf16_gemm<HH, HH, true>,
                         cudaFuncAttributeMaxDynamicSharedMemorySize, GEMM_SMEM);
    cudaFuncSetAttribute((const void*)bf16_gemm<DD, HH, false>,
                         cudaFuncAttributeMaxDynamicSharedMemorySize, GEMM_SMEM);
    cudaFuncSetAttribute((const void*)bf16_gemm<HH, DD, true>,
                         cudaFuncAttributeMaxDynamicSharedMemorySize, GEMM_SMEM);
    cudaFuncSetAttribute((const void*)bf16_dist_argmin,
                         cudaFuncAttributeMaxDynamicSharedMemorySize, DIST_SMEM);

    zero_sums_kernel<<<1, 32>>>();
    convert_all_kernel<<<448, 256>>>((const float4*)We2, (const float4*)We3,
                                     (const float4*)Wd1, (const float4*)Wd2,
                                     (const float4*)E);
    esq_bf_kernel<<<KK / 256, 256>>>();

    // encoder
    layer1_kernel<<<dim3(BB / 128, HH / 128), 256>>>(action, We1, be1, h1);
    bf16_gemm<HH, HH, true ><<<dim3(BB / 128, HH / 128), 256, GEMM_SMEM>>>(h1, We2b, be2, h2);
    bf16_gemm<DD, HH, false><<<dim3(BB / 128, DD / 128), 256, GEMM_SMEM>>>(h2, We3b, be3, enc);

    // codebook
    bf16_dist_argmin<<<BB / 256, 512, DIST_SMEM>>>(enc, Eb);
    vq_gather_kernel<<<BB * DD / 8 / 256, 256>>>(enc, E, q);

    // decoder
    bf16_gemm<HH, DD, true><<<dim3(BB / 128, HH / 128), 256, GEMM_SMEM>>>(q, Wd1b, bd1, h1);
    bf16_gemm<HH, HH, true><<<dim3(BB / 128, HH / 128), 256, GEMM_SMEM>>>(h1, Wd2b, bd2, h2);
    head_loss_kernel<<<BB / 64, 256>>>(h2, Wh, bh, action);

    finalize_kernel<<<1, 1>>>(out);
}

// round 4
// speedup vs baseline: 6.5155x; 1.3805x over previous
#include <cuda_runtime.h>
#include <cuda_bf16.h>
#include <cfloat>
#include <cstdint>

#define BB 32768
#define AA 16
#define HH 256
#define DD 128
#define KK 2048

// ---------------------------------------------------------------------------
// Scratch: bf16 weights/codebook only (activations never leave smem).
// Zero-initialized at module load; padded regions of g_We1b stay zero forever.
// ---------------------------------------------------------------------------
__device__ __nv_bfloat16 g_We1b[HH * 64];    // [256][64], k>=16 zero pad
__device__ __nv_bfloat16 g_We2b[HH * HH];
__device__ __nv_bfloat16 g_We3b[DD * HH];
__device__ __nv_bfloat16 g_Wd1b[HH * DD];
__device__ __nv_bfloat16 g_Wd2b[HH * HH];
__device__ __nv_bfloat16 g_Whb[AA * HH];
__device__ __nv_bfloat16 g_Eb[KK * DD];
__device__ float  g_esq[KK];
__device__ double g_sums[2];

// smem region offsets (dynamic smem, 224KB total)
#define R1_OFF 0        // 64KB: sH1 | (esq/red/bestidx) | sD1
#define R2_OFF 65536    // 64KB: sH2 | sQ | sD2
#define R3_OFF 131072   // 64KB: sActB+wbuf | wbuf | Ebuf | sWh
#define R4_OFF 196608   // 32KB: sEnc
#define SMEM_TOTAL 229376

// ---------------------------------------------------------------------------
// Helpers
// ---------------------------------------------------------------------------
__device__ __forceinline__ unsigned su(const void* p) {
    return (unsigned)__cvta_generic_to_shared(p);
}
__device__ __forceinline__ void cp16(unsigned dst, const void* src) {
    asm volatile("cp.async.cg.shared.global [%0], [%1], 16;\n" :: "r"(dst), "l"(src));
}
__device__ __forceinline__ void cpcommit() { asm volatile("cp.async.commit_group;\n"); }
template <int N>
__device__ __forceinline__ void cpwait() { asm volatile("cp.async.wait_group %0;\n" :: "n"(N)); }

__device__ __forceinline__ void ldm4(unsigned addr, unsigned& r0, unsigned& r1,
                                     unsigned& r2, unsigned& r3) {
    asm volatile("ldmatrix.sync.aligned.m8n8.x4.shared.b16 {%0,%1,%2,%3}, [%4];\n"
                 : "=r"(r0), "=r"(r1), "=r"(r2), "=r"(r3) : "r"(addr));
}
__device__ __forceinline__ void mma_bf16(float* c, unsigned a0, unsigned a1, unsigned a2,
                                         unsigned a3, unsigned b0, unsigned b1) {
    asm volatile(
        "mma.sync.aligned.m16n8k16.row.col.f32.bf16.bf16.f32 "
        "{%0,%1,%2,%3}, {%4,%5,%6,%7}, {%8,%9}, {%0,%1,%2,%3};\n"
        : "+f"(c[0]), "+f"(c[1]), "+f"(c[2]), "+f"(c[3])
        : "r"(a0), "r"(a1), "r"(a2), "r"(a3), "r"(b0), "r"(b1));
}
__device__ __forceinline__ unsigned pack_bf16(float a, float b) {
    __nv_bfloat162 h = __floats2bfloat162_rn(a, b);
    return *reinterpret_cast<unsigned*>(&h);
}

__device__ __forceinline__ void block_reduce_add_to(float v, double* target) {
    __shared__ float sbuf[32];
    int lane = threadIdx.x & 31;
    int wid  = threadIdx.x >> 5;
#pragma unroll
    for (int o = 16; o; o >>= 1) v += __shfl_xor_sync(0xffffffffu, v, o);
    if (lane == 0) sbuf[wid] = v;
    __syncthreads();
    if (wid == 0) {
        v = (lane < 8) ? sbuf[lane] : 0.0f;
#pragma unroll
        for (int o = 4; o; o >>= 1) v += __shfl_xor_sync(0xffffffffu, v, o);
        if (lane == 0) atomicAdd(target, (double)v);
    }
}

// ---------------------------------------------------------------------------
// Convert all weights + codebook fp32 -> bf16.
// float4 segments: We2 16384 | We3 8192 | Wd1 8192 | Wd2 16384 | E 65536 |
//                  We1 1024 (padded dst) | Wh 1024    => 116736 total
// ---------------------------------------------------------------------------
__global__ void convert_all_kernel(const float4* __restrict__ We1, const float4* __restrict__ We2,
                                   const float4* __restrict__ We3, const float4* __restrict__ Wd1,
                                   const float4* __restrict__ Wd2, const float4* __restrict__ Wh,
                                   const float4* __restrict__ E) {
    int i = blockIdx.x * 256 + threadIdx.x;
    const float4* src; uint2* dst; int j, dj;
    if (i < 16384)       { src = We2; dst = (uint2*)g_We2b; j = i;          dj = j; }
    else if (i < 24576)  { src = We3; dst = (uint2*)g_We3b; j = i - 16384;  dj = j; }
    else if (i < 32768)  { src = Wd1; dst = (uint2*)g_Wd1b; j = i - 24576;  dj = j; }
    else if (i < 49152)  { src = Wd2; dst = (uint2*)g_Wd2b; j = i - 32768;  dj = j; }
    else if (i < 114688) { src = E;   dst = (uint2*)g_Eb;   j = i - 49152;  dj = j; }
    else if (i < 115712) { src = We1; dst = (uint2*)g_We1b; j = i - 114688;
                           dj = (j >> 2) * 16 + (j & 3); }   // row n=j>>2, k-quad j&3, row pitch 64
    else                 { src = Wh;  dst = (uint2*)g_Whb;  j = i - 115712; dj = j; }
    float4 v = src[j];
    uint2 p;
    p.x = pack_bf16(v.x, v.y);
    p.y = pack_bf16(v.z, v.w);
    dst[dj] = p;
}

// |bf16(E[n])|^2 (fp32 accum), + zero the loss sums
__global__ void esq_kernel(const float* __restrict__ E) {
    if (blockIdx.x == 0 && threadIdx.x < 2) g_sums[threadIdx.x] = 0.0;
    int n = blockIdx.x * 256 + threadIdx.x;
    const float4* r = reinterpret_cast<const float4*>(E + (size_t)n * DD);
    float s = 0.0f;
#pragma unroll
    for (int i = 0; i < DD / 4; i++) {
        float4 v = r[i];
        float a = __bfloat162float(__float2bfloat16_rn(v.x));
        float b = __bfloat162float(__float2bfloat16_rn(v.y));
        float c = __bfloat162float(__float2bfloat16_rn(v.z));
        float d = __bfloat162float(__float2bfloat16_rn(v.w));
        s += a * a + b * b + c * c + d * d;
    }
    g_esq[n] = s;
}

// ---------------------------------------------------------------------------
// One 128m x 128n GEMM stage: C = act(A_smem[128xK] @ W_gmem[128xK]^T + bias)
// written bf16-swizzled into Ys. W streamed in 64-k chunks, double-buffered.
// 8 warps: wm=w&3 (32m each), wn=w>>2 (64n each). acc[2][8][4].
// ---------------------------------------------------------------------------
template <int K>
__device__ __noinline__ void gemm_stage(
    unsigned Aaddr, int ACH,                       // A smem addr, chunks(16B)/row
    const __nv_bfloat16* __restrict__ Wg,          // W + n0*K
    const float* __restrict__ bias, int n0,
    __nv_bfloat16* __restrict__ Ys, int NYCH, bool relu,
    unsigned wbuf)
{
    constexpr int NCH = K / 64;
    const int tid = threadIdx.x;
    const int w = tid >> 5, L = tid & 31;
    const int wm = w & 3, wn = w >> 2;

    float acc[2][8][4];
#pragma unroll
    for (int a = 0; a < 2; a++)
#pragma unroll
        for (int b = 0; b < 8; b++)
#pragma unroll
            for (int c = 0; c < 4; c++) acc[a][b][c] = 0.0f;

    const int sn = tid >> 1;
    const int scb = (tid & 1) * 4;
    const __nv_bfloat16* Wrow = Wg + (size_t)sn * K;

#pragma unroll
    for (int i = 0; i < 4; i++) {
        int c = scb + i;
        cp16(wbuf + (sn * 8 + (c ^ (sn & 7))) * 16u, Wrow + c * 8);
    }
    cpcommit();

    for (int kc = 0; kc < NCH; kc++) {
        if (kc + 1 < NCH) {
            unsigned dstb = wbuf + ((kc + 1) & 1) * 16384u;
            const __nv_bfloat16* src = Wrow + (kc + 1) * 64;
#pragma unroll
            for (int i = 0; i < 4; i++) {
                int c = scb + i;
                cp16(dstb + (sn * 8 + (c ^ (sn & 7))) * 16u, src + c * 8);
            }
            cpcommit();
            cpwait<1>();
        } else {
            cpwait<0>();
        }
        __syncthreads();

        unsigned Bb = wbuf + (kc & 1) * 16384u;
#pragma unroll
        for (int ks = 0; ks < 4; ks++) {
            unsigned a[2][4];
#pragma unroll
            for (int mt = 0; mt < 2; mt++) {
                int m  = wm * 32 + mt * 16 + (L & 15);
                int ck = kc * 8 + ks * 2 + (L >> 4);
                int sw = (ck & ~7) | ((ck & 7) ^ (m & 7));
                ldm4(Aaddr + (m * ACH + sw) * 16u, a[mt][0], a[mt][1], a[mt][2], a[mt][3]);
            }
#pragma unroll
            for (int np = 0; np < 4; np++) {
                int n   = wn * 64 + np * 16 + (L & 7) + ((L >> 4) << 3);
                int ckb = ks * 2 + ((L >> 3) & 1);
                unsigned b0, b1, b2, b3;
                ldm4(Bb + (n * 8 + (ckb ^ (n & 7))) * 16u, b0, b1, b2, b3);
#pragma unroll
                for (int mt = 0; mt < 2; mt++) {
                    mma_bf16(acc[mt][np * 2 + 0], a[mt][0], a[mt][1], a[mt][2], a[mt][3], b0, b1);
                    mma_bf16(acc[mt][np * 2 + 1], a[mt][0], a[mt][1], a[mt][2], a[mt][3], b2, b3);
                }
            }
        }
        __syncthreads();
    }

    const int g = L >> 2, q2 = (L & 3) * 2;
#pragma unroll
    for (int mt = 0; mt < 2; mt++) {
#pragma unroll
        for (int nt = 0; nt < 8; nt++) {
            int ng = n0 + wn * 64 + nt * 8 + q2;
            float b0 = __ldg(&bias[ng]), b1 = __ldg(&bias[ng + 1]);
            int c  = ng >> 3;
#pragma unroll
            for (int h = 0; h < 2; h++) {
                int m = wm * 32 + mt * 16 + g + 8 * h;
                float v0 = acc[mt][nt][2 * h + 0] + b0;
                float v1 = acc[mt][nt][2 * h + 1] + b1;
                if (relu) { v0 = fmaxf(v0, 0.0f); v1 = fmaxf(v1, 0.0f); }
                int sw = (c & ~7) | ((c & 7) ^ (m & 7));
                *reinterpret_cast<unsigned*>(
                    reinterpret_cast<char*>(Ys) + (m * NYCH + sw) * 16 + (ng & 7) * 2)
                    = pack_bf16(v0, v1);
            }
        }
    }
}

// ---------------------------------------------------------------------------
// Megakernel: per block, 128 rows end-to-end.
// ---------------------------------------------------------------------------
__global__ __launch_bounds__(256, 1)
void mega_kernel(const float* __restrict__ action,
                 const float* __restrict__ be1, const float* __restrict__ be2,
                 const float* __restrict__ be3, const float* __restrict__ E,
                 const float* __restrict__ bd1, const float* __restrict__ bd2,
                 const float* __restrict__ bh) {
    extern __shared__ char sm[];
    const int tid = threadIdx.x;
    const int w = tid >> 5, L = tid & 31;
    const int wm = w & 3, wn = w >> 2;
    const int r0 = blockIdx.x * 128;

    __nv_bfloat16* sH1  = (__nv_bfloat16*)(sm + R1_OFF);
    __nv_bfloat16* sD1  = (__nv_bfloat16*)(sm + R1_OFF);
    __nv_bfloat16* sH2  = (__nv_bfloat16*)(sm + R2_OFF);
    __nv_bfloat16* sQ   = (__nv_bfloat16*)(sm + R2_OFF);
    __nv_bfloat16* sD2  = (__nv_bfloat16*)(sm + R2_OFF);
    __nv_bfloat16* sEnc = (__nv_bfloat16*)(sm + R4_OFF);
    float* sEsq    = (float*)(sm + R1_OFF);
    float* red_v   = (float*)(sm + R1_OFF + 8192);
    int*   red_i   = (int*)  (sm + R1_OFF + 9216);
    int*   bestidx = (int*)  (sm + R1_OFF + 10240);

    // ---------------- Stage 1: h1 = relu(action @ We1^T + be1) ----------------
    {
        char* sActB = sm + R3_OFF;           // 128 x 64 bf16 (k padded), swizzled
        int m = tid >> 1, hf = tid & 1;
        const float* ap = action + (size_t)(r0 + m) * AA + hf * 8;
        float4 f0 = __ldg((const float4*)ap);
        float4 f1 = __ldg((const float4*)(ap + 4));
        uint4 pk;
        pk.x = pack_bf16(f0.x, f0.y); pk.y = pack_bf16(f0.z, f0.w);
        pk.z = pack_bf16(f1.x, f1.y); pk.w = pack_bf16(f1.z, f1.w);
        *reinterpret_cast<uint4*>(sActB + (m * 8 + (hf ^ (m & 7))) * 16) = pk;
        uint4 z = make_uint4(0, 0, 0, 0);
#pragma unroll
        for (int c = 2 + hf; c < 8; c += 2)
            *reinterpret_cast<uint4*>(sActB + (m * 8 + (c ^ (m & 7))) * 16) = z;
        __syncthreads();

        unsigned wb = su(sm + R3_OFF + 16384);
        gemm_stage<64>(su(sActB), 8, g_We1b,             be1, 0,   sH1, 32, true, wb);
        gemm_stage<64>(su(sActB), 8, g_We1b + 128 * 64,  be1, 128, sH1, 32, true, wb);
    }
    __syncthreads();

    // ---------------- Stage 2: h2 = relu(h1 @ We2^T + be2) ----------------
    {
        unsigned wb = su(sm + R3_OFF);
        gemm_stage<256>(su(sH1), 32, g_We2b,             be2, 0,   sH2, 32, true, wb);
        gemm_stage<256>(su(sH1), 32, g_We2b + 128 * 256, be2, 128, sH2, 32, true, wb);
    }
    __syncthreads();

    // ---------------- Stage 3: enc = h2 @ We3^T + be3 ----------------
    gemm_stage<256>(su(sH2), 32, g_We3b, be3, 0, sEnc, 16, false, su(sm + R3_OFF));
    __syncthreads();

    // ---------------- Stage 4: dist + argmin over 2048 codes ----------------
    {
        unsigned ebuf = su(sm + R3_OFF);        // 2 x 32KB E tiles
        unsigned eaddr = su(sEnc);

        // group 0: esq + E tile 0
#pragma unroll
        for (int t = 0; t < 2; t++) {
            int idx = tid + t * 256;
            cp16(su(sEsq) + idx * 16u, g_esq + idx * 4);
        }
#pragma unroll
        for (int t = 0; t < 8; t++) {
            int idx = tid + t * 256;
            int n = idx >> 4, c = idx & 15;
            int sw = (c & 8) | ((c & 7) ^ (n & 7));
            cp16(ebuf + (n * 16 + sw) * 16u, g_Eb + (size_t)n * DD + c * 8);
        }
        cpcommit();

        float bestv[4];
        int   besti[4];
#pragma unroll
        for (int i = 0; i < 4; i++) { bestv[i] = FLT_MAX; besti[i] = 0; }

        for (int t0 = 0; t0 < 16; t0++) {
            if (t0 + 1 < 16) {
                unsigned bb = ebuf + ((t0 + 1) & 1) * 32768u;
                const __nv_bfloat16* Eg = g_Eb + (size_t)(t0 + 1) * 128 * DD;
#pragma unroll
                for (int t = 0; t < 8; t++) {
                    int idx = tid + t * 256;
                    int n = idx >> 4, c = idx & 15;
                    int sw = (c & 8) | ((c & 7) ^ (n & 7));
                    cp16(bb + (n * 16 + sw) * 16u, Eg + (size_t)n * DD + c * 8);
                }
                cpcommit();
                cpwait<1>();
            } else {
                cpwait<0>();
            }
            __syncthreads();

            unsigned Bb = ebuf + (t0 & 1) * 32768u;
            float acc[2][8][4];
#pragma unroll
            for (int a = 0; a < 2; a++)
#pragma unroll
                for (int b = 0; b < 8; b++)
#pragma unroll
                    for (int c = 0; c < 4; c++) acc[a][b][c] = 0.0f;

#pragma unroll
            for (int ks = 0; ks < 8; ks++) {
                unsigned a[2][4];
#pragma unroll
                for (int mt = 0; mt < 2; mt++) {
                    int m  = wm * 32 + mt * 16 + (L & 15);
                    int ck = ks * 2 + (L >> 4);
                    int sw = (ck & 8) | ((ck & 7) ^ (m & 7));
                    ldm4(eaddr + (m * 16 + sw) * 16u, a[mt][0], a[mt][1], a[mt][2], a[mt][3]);
                }
#pragma unroll
                for (int np = 0; np < 4; np++) {
                    int n   = wn * 64 + np * 16 + (L & 7) + ((L >> 4) << 3);
                    int ckb = ks * 2 + ((L >> 3) & 1);
                    int sw  = (ckb & 8) | ((ckb & 7) ^ (n & 7));
                    unsigned b0, b1, b2, b3;
                    ldm4(Bb + (n * 16 + sw) * 16u, b0, b1, b2, b3);
#pragma unroll
                    for (int mt = 0; mt < 2; mt++) {
                        mma_bf16(acc[mt][np * 2 + 0], a[mt][0], a[mt][1], a[mt][2], a[mt][3], b0, b1);
                        mma_bf16(acc[mt][np * 2 + 1], a[mt][0], a[mt][1], a[mt][2], a[mt][3], b2, b3);
                    }
                }
            }

            const int q2 = (L & 3) * 2;
#pragma unroll
            for (int nt = 0; nt < 8; nt++) {
                int n = t0 * 128 + wn * 64 + nt * 8 + q2;
                float es0 = sEsq[n - t0 * 128 + t0 * 128];  // = sEsq index n (local==global here)
                float es1 = sEsq[n + 1 - t0 * 128 + t0 * 128];
                es0 = sEsq[(n) & (KK - 1)];
                es1 = sEsq[(n + 1) & (KK - 1)];
#pragma unroll
                for (int mt = 0; mt < 2; mt++) {
#pragma unroll
                    for (int h = 0; h < 2; h++) {
                        int r = mt * 2 + h;
                        float v0 = fmaf(-2.0f, acc[mt][nt][2 * h + 0], es0);
                        float v1 = fmaf(-2.0f, acc[mt][nt][2 * h + 1], es1);
                        if (v0 < bestv[r]) { bestv[r] = v0; besti[r] = n; }
                        if (v1 < bestv[r]) { bestv[r] = v1; besti[r] = n + 1; }
                    }
                }
            }
            __syncthreads();
        }

        // quad reduce (lanes sharing the same row)
#pragma unroll
        for (int r = 0; r < 4; r++) {
            float v = bestv[r];
            int   ii = besti[r];
#pragma unroll
            for (int o = 1; o <= 2; o <<= 1) {
                float v2 = __shfl_xor_sync(0xffffffffu, v, o);
                int   i2 = __shfl_xor_sync(0xffffffffu, ii, o);
                if (v2 < v || (v2 == v && i2 < ii)) { v = v2; ii = i2; }
            }
            bestv[r] = v; besti[r] = ii;
        }
        if ((L & 3) == 0) {
            int g = L >> 2;
#pragma unroll
            for (int r = 0; r < 4; r++) {
                int mt = r >> 1, h = r & 1;
                int row = wm * 32 + mt * 16 + g + 8 * h;
                red_v[row * 2 + wn] = bestv[r];
                red_i[row * 2 + wn] = besti[r];
            }
        }
        __syncthreads();
        if (tid < 128) {
            float v0 = red_v[tid * 2], v1 = red_v[tid * 2 + 1];
            int   i0 = red_i[tid * 2], i1 = red_i[tid * 2 + 1];
            bestidx[tid] = (v1 < v0 || (v1 == v0 && i1 < i0)) ? i1 : i0;
        }
        __syncthreads();
    }

    // ---------------- Stage 5: gather q = E[idx], vq loss ----------------
    {
        int m = tid >> 1, hf = tid & 1;
        int code = bestidx[m];
        const float4* Ep = reinterpret_cast<const float4*>(E + ((size_t)code << 7) + hf * 64);
        float s = 0.0f;
#pragma unroll
        for (int j = 0; j < 8; j++) {
            int c = hf * 8 + j;
            float4 q0 = __ldg(&Ep[2 * j]);
            float4 q1 = __ldg(&Ep[2 * j + 1]);
            int sw = (c & 8) | ((c & 7) ^ (m & 7));
            uint4 ev = *reinterpret_cast<uint4*>(
                reinterpret_cast<char*>(sEnc) + (m * 16 + sw) * 16);
            const __nv_bfloat162* eh = reinterpret_cast<const __nv_bfloat162*>(&ev);
            float2 e0 = __bfloat1622float2(eh[0]);
            float2 e1 = __bfloat1622float2(eh[1]);
            float2 e2 = __bfloat1622float2(eh[2]);
            float2 e3 = __bfloat1622float2(eh[3]);
            float d;
            d = e0.x - q0.x; s += d * d;  d = e0.y - q0.y; s += d * d;
            d = e1.x - q0.z; s += d * d;  d = e1.y - q0.w; s += d * d;
            d = e2.x - q1.x; s += d * d;  d = e2.y - q1.y; s += d * d;
            d = e3.x - q1.z; s += d * d;  d = e3.y - q1.w; s += d * d;
            uint4 pk;
            pk.x = pack_bf16(q0.x, q0.y); pk.y = pack_bf16(q0.z, q0.w);
            pk.z = pack_bf16(q1.x, q1.y); pk.w = pack_bf16(q1.z, q1.w);
            *reinterpret_cast<uint4*>(
                reinterpret_cast<char*>(sQ) + (m * 16 + sw) * 16) = pk;
        }
        block_reduce_add_to(s, &g_sums[0]);
    }
    __syncthreads();

    // ---------------- Stage 6/7: decoder ----------------
    {
        unsigned wb = su(sm + R3_OFF);
        gemm_stage<128>(su(sQ), 16, g_Wd1b,             bd1, 0,   sD1, 32, true, wb);
        gemm_stage<128>(su(sQ), 16, g_Wd1b + 128 * 128, bd1, 128, sD1, 32, true, wb);
        __syncthreads();
        gemm_stage<256>(su(sD1), 32, g_Wd2b,             bd2, 0,   sD2, 32, true, wb);
        gemm_stage<256>(su(sD1), 32, g_Wd2b + 128 * 256, bd2, 128, sD2, 32, true, wb);
    }
    __syncthreads();

    // ---------------- Stage 8: head mma + tanh + recons loss ----------------
    {
        unsigned whaddr = su(sm + R3_OFF);     // 16 x 256 bf16 swizzled (8KB)
#pragma unroll
        for (int i = 0; i < 2; i++) {
            int idx = tid * 2 + i;
            int n = idx >> 5, c = idx & 31;
            int sw = (c & 24) | ((c & 7) ^ (n & 7));
            cp16(whaddr + (n * 32 + sw) * 16u, g_Whb + (size_t)n * HH + c * 8);
        }
        cpcommit(); cpwait<0>();
        __syncthreads();

        unsigned daddr = su(sD2);
        float acc[2][4];
#pragma unroll
        for (int a = 0; a < 2; a++)
#pragma unroll
            for (int c = 0; c < 4; c++) acc[a][c] = 0.0f;

#pragma unroll
        for (int ks = 0; ks < 16; ks++) {
            int m  = w * 16 + (L & 15);
            int ck = ks * 2 + (L >> 4);
            int sw = (ck & 24) | ((ck & 7) ^ (m & 7));
            unsigned a0, a1, a2, a3;
            ldm4(daddr + (m * 32 + sw) * 16u, a0, a1, a2, a3);
            int n   = (L & 7) + ((L >> 4) << 3);
            int ckb = ks * 2 + ((L >> 3) & 1);
            int swb = (ckb & 24) | ((ckb & 7) ^ (n & 7));
            unsigned b0, b1, b2, b3;
            ldm4(whaddr + (n * 32 + swb) * 16u, b0, b1, b2, b3);
            mma_bf16(acc[0], a0, a1, a2, a3, b0, b1);
            mma_bf16(acc[1], a0, a1, a2, a3, b2, b3);
        }

        const int g = L >> 2, q2 = (L & 3) * 2;
        float s = 0.0f;
#pragma unroll
        for (int nt = 0; nt < 2; nt++) {
            int n = nt * 8 + q2;
            float b0 = __ldg(&bh[n]), b1 = __ldg(&bh[n + 1]);
#pragma unroll
            for (int h = 0; h < 2; h++) {
                int m = w * 16 + g + 8 * h;
                const float* ar = action + (size_t)(r0 + m) * AA + n;
                float t0 = tanhf(acc[nt][2 * h + 0] + b0) - __ldg(&ar[0]);
                float t1 = tanhf(acc[nt][2 * h + 1] + b1) - __ldg(&ar[1]);
                s += t0 * t0 + t1 * t1;
            }
        }
        block_reduce_add_to(s, &g_sums[1]);
    }
}

__global__ void finalize_kernel(float* __restrict__ out) {
    double vq  = g_sums[0] / ((double)BB * (double)DD);
    double rec = g_sums[1] / ((double)BB * (double)AA);
    out[0] = (float)(rec + 1.25 * vq);
}

// ---------------------------------------------------------------------------
// Launch
// ---------------------------------------------------------------------------
extern "C" void kernel_launch(void* const* d_in, const int* in_sizes, int n_in,
                              void* d_out, int out_size) {
    const float* action = (const float*)d_in[0];
    const float* We1    = (const float*)d_in[1];
    const float* be1    = (const float*)d_in[2];
    const float* We2    = (const float*)d_in[3];
    const float* be2    = (const float*)d_in[4];
    const float* We3    = (const float*)d_in[5];
    const float* be3    = (const float*)d_in[6];
    const float* E      = (const float*)d_in[7];
    const float* Wd1    = (const float*)d_in[8];
    const float* bd1    = (const float*)d_in[9];
    const float* Wd2    = (const float*)d_in[10];
    const float* bd2    = (const float*)d_in[11];
    const float* Wh     = (const float*)d_in[12];
    const float* bh     = (const float*)d_in[13];
    float* out = (float*)d_out;

    cudaFuncSetAttribute((const void*)mega_kernel,
                         cudaFuncAttributeMaxDynamicSharedMemorySize, SMEM_TOTAL);

    convert_all_kernel<<<456, 256>>>((const float4*)We1, (const float4*)We2,
                                     (const float4*)We3, (const float4*)Wd1,
                                     (const float4*)Wd2, (const float4*)Wh,
                                     (const float4*)E);
    esq_kernel<<<KK / 256, 256>>>(E);
    mega_kernel<<<BB / 128, 256, SMEM_TOTAL>>>(action, be1, be2, be3, E, bd1, bd2, bh);
    finalize_kernel<<<1, 1>>>(out);
}